// round 5
// baseline (speedup 1.0000x reference)
#include <cuda_runtime.h>
#include <cuda_bf16.h>

// Problem dims (fixed by the dataset)
#define D_   3072
#define H_   1024
#define Z_   32
#define BS_  128
#define NN_  32
#define MNN  4096   // BS_*NN_
#define MALL 4224   // BS_ + MNN

// ---------------------------------------------------------------------------
// Static scratch (allocation-free rule: __device__ globals)
// ---------------------------------------------------------------------------
__device__ float g_h1[MALL * H_];     // encoder h1, later t_h1
__device__ float g_h2[MALL * H_];     // encoder h2, later t_h2
__device__ float g_Z[MALL * Z_];      // latent codes (rows 0..127 = z_c, rest z_nn)
__device__ float g_dz[MNN * Z_];      // z_nn - z_c
__device__ float g_h1c[BS_ * H_];     // decoder center h1 (relu'd; >0 == mask1)
__device__ float g_h2c[BS_ * H_];     // decoder center h2 (relu'd; >0 == mask2)
__device__ float g_recon[BS_ * D_];   // decoder center output
__device__ float g_w[MNN];            // binary kernel weights
__device__ float g_lpart[24 * 32];    // per-block loss partials (loss gemm grid)

// ---------------------------------------------------------------------------
// Tiled SGEMM: C(MxN) = A(MxK) @ B(KxN), all row-major.
// BM=BN=128, BK=8, 256 threads, 8x8 per thread.
// M = gridDim.y*128 (exact), N multiple of 128, K multiple of 8.
// EPI: 1 = +bias, relu; 2 = +bias; 3 = center-row mask (mask[(r>>5)*N+c] > 0)
// ---------------------------------------------------------------------------
template <int EPI>
__global__ void __launch_bounds__(256) gemm128(
    const float* __restrict__ A, const float* __restrict__ B,
    float* __restrict__ C, const float* __restrict__ bias,
    const float* __restrict__ mask, int K, int N)
{
    __shared__ float As[8][128];
    __shared__ float Bs[8][128];

    const int tid  = threadIdx.x;
    const int rb   = blockIdx.y * 128;
    const int cb   = blockIdx.x * 128;
    const int arow = tid >> 1;            // 0..127
    const int akc  = (tid & 1) * 4;       // 0 or 4
    const int brow = tid >> 5;            // 0..7
    const int bcol = (tid & 31) * 4;      // 0..124
    const int trow = (tid >> 4) * 8;      // 0..120
    const int tcol = (tid & 15) * 8;      // 0..120

    const float* Aptr = A + (size_t)(rb + arow) * K + akc;
    const float* Bptr = B + (size_t)brow * N + cb + bcol;

    float acc[8][8];
#pragma unroll
    for (int i = 0; i < 8; i++)
#pragma unroll
        for (int j = 0; j < 8; j++) acc[i][j] = 0.f;

    for (int kt = 0; kt < K; kt += 8) {
        float4 av = *(const float4*)(Aptr + kt);
        float4 bv = *(const float4*)(Bptr + (size_t)kt * N);
        __syncthreads();
        As[akc + 0][arow] = av.x;
        As[akc + 1][arow] = av.y;
        As[akc + 2][arow] = av.z;
        As[akc + 3][arow] = av.w;
        *(float4*)&Bs[brow][bcol] = bv;
        __syncthreads();
#pragma unroll
        for (int k = 0; k < 8; k++) {
            float4 a0 = *(const float4*)&As[k][trow];
            float4 a1 = *(const float4*)&As[k][trow + 4];
            float4 b0 = *(const float4*)&Bs[k][tcol];
            float4 b1 = *(const float4*)&Bs[k][tcol + 4];
            float ar[8] = {a0.x, a0.y, a0.z, a0.w, a1.x, a1.y, a1.z, a1.w};
            float br[8] = {b0.x, b0.y, b0.z, b0.w, b1.x, b1.y, b1.z, b1.w};
#pragma unroll
            for (int i = 0; i < 8; i++)
#pragma unroll
                for (int j = 0; j < 8; j++) acc[i][j] += ar[i] * br[j];
        }
    }

    const int cc = cb + tcol;
#pragma unroll
    for (int i = 0; i < 8; i++) {
        const int r = rb + trow + i;
        float o[8];
#pragma unroll
        for (int j = 0; j < 8; j++) o[j] = acc[i][j];
        if (EPI == 1 || EPI == 2) {
#pragma unroll
            for (int j = 0; j < 8; j++) o[j] += bias[cc + j];
            if (EPI == 1) {
#pragma unroll
                for (int j = 0; j < 8; j++) o[j] = fmaxf(o[j], 0.f);
            }
        } else if (EPI == 3) {
            const float* mr = mask + (size_t)(r >> 5) * N + cc;
#pragma unroll
            for (int j = 0; j < 8; j++) o[j] = (mr[j] > 0.f) ? o[j] : 0.f;
        }
        float4* Cp = (float4*)(C + (size_t)r * N + cc);
        Cp[0] = make_float4(o[0], o[1], o[2], o[3]);
        Cp[1] = make_float4(o[4], o[5], o[6], o[7]);
    }
}

// ---------------------------------------------------------------------------
// Same GEMM core but with the loss epilogue fused:
// jac = A@B ; e = x_nn - recon[b] - jac ; lpart += w[row]*e^2
// A = t_h2 (4096x1024), B = Wd3 (1024x3072). No bias (directional derivative).
// ---------------------------------------------------------------------------
__global__ void __launch_bounds__(256) gemm128_loss(
    const float* __restrict__ A, const float* __restrict__ B,
    const float* __restrict__ xnn, const float* __restrict__ recon,
    int K, int N)
{
    __shared__ float As[8][128];
    __shared__ float Bs[8][128];

    const int tid  = threadIdx.x;
    const int rb   = blockIdx.y * 128;
    const int cb   = blockIdx.x * 128;
    const int arow = tid >> 1;
    const int akc  = (tid & 1) * 4;
    const int brow = tid >> 5;
    const int bcol = (tid & 31) * 4;
    const int trow = (tid >> 4) * 8;
    const int tcol = (tid & 15) * 8;

    const float* Aptr = A + (size_t)(rb + arow) * K + akc;
    const float* Bptr = B + (size_t)brow * N + cb + bcol;

    float acc[8][8];
#pragma unroll
    for (int i = 0; i < 8; i++)
#pragma unroll
        for (int j = 0; j < 8; j++) acc[i][j] = 0.f;

    for (int kt = 0; kt < K; kt += 8) {
        float4 av = *(const float4*)(Aptr + kt);
        float4 bv = *(const float4*)(Bptr + (size_t)kt * N);
        __syncthreads();
        As[akc + 0][arow] = av.x;
        As[akc + 1][arow] = av.y;
        As[akc + 2][arow] = av.z;
        As[akc + 3][arow] = av.w;
        *(float4*)&Bs[brow][bcol] = bv;
        __syncthreads();
#pragma unroll
        for (int k = 0; k < 8; k++) {
            float4 a0 = *(const float4*)&As[k][trow];
            float4 a1 = *(const float4*)&As[k][trow + 4];
            float4 b0 = *(const float4*)&Bs[k][tcol];
            float4 b1 = *(const float4*)&Bs[k][tcol + 4];
            float ar[8] = {a0.x, a0.y, a0.z, a0.w, a1.x, a1.y, a1.z, a1.w};
            float br[8] = {b0.x, b0.y, b0.z, b0.w, b1.x, b1.y, b1.z, b1.w};
#pragma unroll
            for (int i = 0; i < 8; i++)
#pragma unroll
                for (int j = 0; j < 8; j++) acc[i][j] += ar[i] * br[j];
        }
    }

    const int cc = cb + tcol;
    float lsum = 0.f;
#pragma unroll
    for (int i = 0; i < 8; i++) {
        const int r = rb + trow + i;
        const int b = r >> 5;
        const float wr = g_w[r];
        const float* xr = xnn + (size_t)r * N + cc;
        const float* rr = recon + (size_t)b * N + cc;
        float4 x0 = *(const float4*)xr;
        float4 x1 = *(const float4*)(xr + 4);
        float4 r0 = *(const float4*)rr;
        float4 r1 = *(const float4*)(rr + 4);
        float xv[8] = {x0.x, x0.y, x0.z, x0.w, x1.x, x1.y, x1.z, x1.w};
        float rv[8] = {r0.x, r0.y, r0.z, r0.w, r1.x, r1.y, r1.z, r1.w};
#pragma unroll
        for (int j = 0; j < 8; j++) {
            float e = xv[j] - rv[j] - acc[i][j];
            lsum += wr * e * e;
        }
    }

    // block reduce (deterministic partials, no atomics)
#pragma unroll
    for (int o = 16; o; o >>= 1) lsum += __shfl_down_sync(0xffffffffu, lsum, o);
    __shared__ float red[8];
    if ((tid & 31) == 0) red[tid >> 5] = lsum;
    __syncthreads();
    if (tid == 0) {
        float t = 0.f;
#pragma unroll
        for (int i = 0; i < 8; i++) t += red[i];
        g_lpart[blockIdx.y * gridDim.x + blockIdx.x] = t;
    }
}

// ---------------------------------------------------------------------------
// Skinny GEMM for encoder layer 3: C(Mx32) = A(MxK) @ B(Kx32) + bias
// One output per thread; 8 rows x 32 cols per 256-thread block.
// ---------------------------------------------------------------------------
__global__ void __launch_bounds__(256) fc_skinny32(
    const float* __restrict__ A, const float* __restrict__ B,
    const float* __restrict__ bias, float* __restrict__ C, int K)
{
    const int r = blockIdx.x * 8 + (threadIdx.x >> 5);
    const int c = threadIdx.x & 31;
    const float* arow = A + (size_t)r * K;
    float s = 0.f;
#pragma unroll 8
    for (int k = 0; k < K; k++) s += __ldg(arow + k) * __ldg(B + (size_t)k * 32 + c);
    C[(size_t)r * 32 + c] = s + bias[c];
}

// dz[row][k] = z_nn[row][k] - z_c[row>>5][k]
__global__ void dz_kernel()
{
    const int i = blockIdx.x * 256 + threadIdx.x;  // 0 .. MNN*Z_-1
    const int row = i >> 5;
    const int k = i & 31;
    g_dz[i] = g_Z[(BS_ + row) * Z_ + k] - g_Z[(row >> 5) * Z_ + k];
}

// binary kernel weights: 1.0 if ||x_c[b]-x_nn[b,n]|| > 1e-12 else 0.5
__global__ void __launch_bounds__(128) weights_kernel(
    const float* __restrict__ xc, const float* __restrict__ xnn)
{
    const int row = blockIdx.x;
    const int b = row >> 5;
    const float4* a = (const float4*)(xc + (size_t)b * D_);
    const float4* x = (const float4*)(xnn + (size_t)row * D_);
    float s = 0.f;
    for (int d = threadIdx.x; d < D_ / 4; d += 128) {
        float4 av = a[d], xv = x[d];
        float dx = av.x - xv.x, dy = av.y - xv.y, dz2 = av.z - xv.z, dw = av.w - xv.w;
        s += dx * dx + dy * dy + dz2 * dz2 + dw * dw;
    }
#pragma unroll
    for (int o = 16; o; o >>= 1) s += __shfl_down_sync(0xffffffffu, s, o);
    __shared__ float red[4];
    if ((threadIdx.x & 31) == 0) red[threadIdx.x >> 5] = s;
    __syncthreads();
    if (threadIdx.x == 0) {
        float t = red[0] + red[1] + red[2] + red[3];
        g_w[row] = (t > 1e-24f) ? 1.0f : 0.5f;   // dist > EPS  <=>  dist^2 > EPS^2
    }
}

__global__ void final_reduce(float* __restrict__ out)
{
    float s = 0.f;
    for (int i = threadIdx.x; i < 24 * 32; i += 256) s += g_lpart[i];
#pragma unroll
    for (int o = 16; o; o >>= 1) s += __shfl_down_sync(0xffffffffu, s, o);
    __shared__ float red[8];
    if ((threadIdx.x & 31) == 0) red[threadIdx.x >> 5] = s;
    __syncthreads();
    if (threadIdx.x == 0) {
        float t = 0.f;
#pragma unroll
        for (int i = 0; i < 8; i++) t += red[i];
        out[0] = t * (1.0f / (float)(BS_ * NN_));
    }
}

// ---------------------------------------------------------------------------
// Launch plan.
//   Key simplification: decoder is a ReLU MLP => piecewise linear => the
//   nested-jvp "hess" term in the reference is exactly zero. So:
//     n_recon[b,n] = recon[b] + J(z_c[b]) . (z_nn[b,n] - z_c[b])
//   with JVP masks taken from the CENTER's pre-activations.
// ---------------------------------------------------------------------------
extern "C" void kernel_launch(void* const* d_in, const int* in_sizes, int n_in,
                              void* d_out, int out_size)
{
    const float* x_c  = (const float*)d_in[0];
    const float* x_nn = (const float*)d_in[1];
    const float* We1  = (const float*)d_in[2];
    const float* be1  = (const float*)d_in[3];
    const float* We2  = (const float*)d_in[4];
    const float* be2  = (const float*)d_in[5];
    const float* We3  = (const float*)d_in[6];
    const float* be3  = (const float*)d_in[7];
    const float* Wd1  = (const float*)d_in[8];
    const float* bd1  = (const float*)d_in[9];
    const float* Wd2  = (const float*)d_in[10];
    const float* bd2  = (const float*)d_in[11];
    const float* Wd3  = (const float*)d_in[12];
    const float* bd3  = (const float*)d_in[13];
    float* out = (float*)d_out;

    float *h1, *h2, *Zb, *dz, *h1c, *h2c, *recon;
    cudaGetSymbolAddress((void**)&h1, g_h1);
    cudaGetSymbolAddress((void**)&h2, g_h2);
    cudaGetSymbolAddress((void**)&Zb, g_Z);
    cudaGetSymbolAddress((void**)&dz, g_dz);
    cudaGetSymbolAddress((void**)&h1c, g_h1c);
    cudaGetSymbolAddress((void**)&h2c, g_h2c);
    cudaGetSymbolAddress((void**)&recon, g_recon);

    const dim3 t(256);

    // Encoder: rows 0..127 = x_c, rows 128..4223 = x_nn (flattened)
    gemm128<1><<<dim3(8, 1), t>>>(x_c,  We1, h1,              be1, nullptr, D_, H_);
    gemm128<1><<<dim3(8, 32), t>>>(x_nn, We1, h1 + BS_ * H_,  be1, nullptr, D_, H_);
    gemm128<1><<<dim3(8, 33), t>>>(h1,   We2, h2,             be2, nullptr, H_, H_);
    fc_skinny32<<<MALL / 8, 256>>>(h2, We3, be3, Zb, H_);

    // dz = z_nn - z_c
    dz_kernel<<<(MNN * Z_) / 256, 256>>>();

    // Center decoder path (activations double as JVP masks)
    gemm128<1><<<dim3(8, 1), t>>>(Zb,  Wd1, h1c,   bd1, nullptr, Z_, H_);
    gemm128<1><<<dim3(8, 1), t>>>(h1c, Wd2, h2c,   bd2, nullptr, H_, H_);
    gemm128<2><<<dim3(24, 1), t>>>(h2c, Wd3, recon, bd3, nullptr, H_, D_);

    // JVP chain (reuse encoder scratch): t_h1 -> g_h1, t_h2 -> g_h2
    gemm128<3><<<dim3(8, 32), t>>>(dz, Wd1, h1, nullptr, h1c, Z_, H_);
    gemm128<3><<<dim3(8, 32), t>>>(h1, Wd2, h2, nullptr, h2c, H_, H_);

    // Binary-kernel weights
    weights_kernel<<<MNN, 128>>>(x_c, x_nn);

    // Final GEMM (jac = t_h2 @ Wd3) with fused weighted squared-error loss
    gemm128_loss<<<dim3(24, 32), t>>>(h2, Wd3, x_nn, recon, H_, D_);
    final_reduce<<<1, 256>>>(out);
}

// round 7
// speedup vs baseline: 6.1472x; 6.1472x over previous
#include <cuda_runtime.h>
#include <cuda_bf16.h>
#include <cstdint>

#define D_   3072
#define H_   1024
#define Z_   32
#define BS_  128
#define NN_  32
#define MNN  4096   // BS_*NN_
#define MALL 4224   // BS_ + MNN

// ---------------------------------------------------------------------------
// Static scratch (allocation-free rule)
// ---------------------------------------------------------------------------
__device__ __align__(16) __nv_bfloat16 g_xa[MALL * D_];    // [x_c; x_nn] bf16
__device__ __align__(16) __nv_bfloat16 g_h1b[MALL * H_];   // enc h1 / jvp t1
__device__ __align__(16) __nv_bfloat16 g_h2b[MALL * H_];   // enc h2 / jvp t2
__device__ __align__(16) __nv_bfloat16 g_We1t[H_ * D_];    // We1^T [N,K] bf16
__device__ __align__(16) __nv_bfloat16 g_We2t[H_ * H_];
__device__ __align__(16) __nv_bfloat16 g_Wd1t[H_ * 64];    // Wd1^T, K pad 32->64
__device__ __align__(16) __nv_bfloat16 g_Wd2t[H_ * H_];
__device__ __align__(16) __nv_bfloat16 g_Wd3t[D_ * H_];
__device__ __align__(16) __nv_bfloat16 g_zcb[BS_ * 64];    // z_c bf16, padded
__device__ __align__(16) __nv_bfloat16 g_dzb[MNN * 64];    // dz bf16, padded
__device__ __align__(16) __nv_bfloat16 g_h1cb[BS_ * H_];   // center dec h1 (mask1)
__device__ __align__(16) __nv_bfloat16 g_h2cb[BS_ * H_];   // center dec h2 (mask2)
__device__ float g_z32[MALL * Z_];
__device__ float g_recon[BS_ * D_];
__device__ float g_w[MNN];
__device__ float g_lpart[768];

// ---------------------------------------------------------------------------
// PTX helpers (all plain sm_80+ PTX: works on target sm_103)
// ---------------------------------------------------------------------------
__device__ __forceinline__ uint32_t smem_u32(const void* p)
{
    uint32_t a;
    asm("{ .reg .u64 t; cvta.to.shared.u64 t, %1; cvt.u32.u64 %0, t; }"
        : "=r"(a) : "l"(p));
    return a;
}
#define CP_ASYNC16(dst, src) \
    asm volatile("cp.async.cg.shared.global [%0], [%1], 16;" \
                 :: "r"(dst), "l"(src) : "memory")
#define CP_COMMIT()  asm volatile("cp.async.commit_group;" ::: "memory")
#define CP_WAIT2()   asm volatile("cp.async.wait_group 2;" ::: "memory")

__device__ __forceinline__ void ldmx4(uint32_t* r, uint32_t addr)
{
    asm volatile("ldmatrix.sync.aligned.m8n8.x4.shared.b16 {%0,%1,%2,%3}, [%4];"
                 : "=r"(r[0]), "=r"(r[1]), "=r"(r[2]), "=r"(r[3]) : "r"(addr));
}
__device__ __forceinline__ void mma_bf16(float* c, const uint32_t* a,
                                         uint32_t b0, uint32_t b1)
{
    asm volatile(
        "mma.sync.aligned.m16n8k16.row.col.f32.bf16.bf16.f32 "
        "{%0,%1,%2,%3}, {%4,%5,%6,%7}, {%8,%9}, {%0,%1,%2,%3};"
        : "+f"(c[0]), "+f"(c[1]), "+f"(c[2]), "+f"(c[3])
        : "r"(a[0]), "r"(a[1]), "r"(a[2]), "r"(a[3]), "r"(b0), "r"(b1));
}
__device__ __forceinline__ uint32_t sw128(uint32_t o) { return o ^ ((o >> 3) & 0x70); }

// ---------------------------------------------------------------------------
// Warp-MMA GEMM: C[M,N] = A[M,K] @ Bt[N,K]^T  (bf16 in, fp32 accum)
// Block 128x128, BK=64, 8 warps (2x4), warp tile 64x32, 3-stage cp.async.
// EPI: 1 bias+relu->bf16 | 3 bias->f32 | 4 mask(bf16>0)->bf16 | 5 fused loss
// ---------------------------------------------------------------------------
static constexpr int STAGE_BYTES = 32768;           // A 16KB + B 16KB
static constexpr int SMEM_BYTES  = 3 * STAGE_BYTES; // 96KB

template <int EPI>
__global__ void __launch_bounds__(256, 2) tgemm(
    const __nv_bfloat16* __restrict__ A, const __nv_bfloat16* __restrict__ Bt,
    int K, int N,
    __nv_bfloat16* __restrict__ Cb, float* __restrict__ Cf,
    const float* __restrict__ bias, const __nv_bfloat16* __restrict__ maskp,
    const float* __restrict__ xnn, const float* __restrict__ recon,
    const float* __restrict__ wrow, float* __restrict__ lpart)
{
    extern __shared__ __align__(128) char smem[];
    const uint32_t sb = smem_u32(smem);
    const int tid = threadIdx.x, lane = tid & 31, wid = tid >> 5;
    const int wm = wid & 1, wn = wid >> 1;           // 2 x 4 warp grid
    const int rb = blockIdx.y << 7, cbase = blockIdx.x << 7;

    float acc[4][4][4];
#pragma unroll
    for (int i = 0; i < 4; i++)
#pragma unroll
        for (int j = 0; j < 4; j++)
#pragma unroll
            for (int q = 0; q < 4; q++) acc[i][j][q] = 0.f;

    const int nk = K >> 6;

    // per-thread cp.async mapping: 4 x 16B for A + 4 x 16B for B per stage
    const int ldid0 = tid;                 // id = tid + i*256 ; row=id>>3, c=id&7
    // ldmatrix base offsets (bytes within a 128-row x 128B stage tile)
    const int aBase = (wm * 64 + (lane & 15)) * 128 + ((lane >> 4) * 16);
    const int bBase = (wn * 32 + (lane & 7) + ((lane >> 4) * 8)) * 128
                    + (((lane >> 3) & 1) * 16);

    // ---- prologue: fill up to 3 stages
#pragma unroll
    for (int s = 0; s < 3; s++) {
        if (s < nk) {
            const uint32_t sa = sb + s * STAGE_BYTES;
#pragma unroll
            for (int i = 0; i < 4; i++) {
                int id = ldid0 + i * 256;
                int row = id >> 3, c = id & 7;
                uint32_t sw = sw128(row * 128 + c * 16);
                CP_ASYNC16(sa + sw,
                           A + (size_t)(rb + row) * K + s * 64 + c * 8);
                CP_ASYNC16(sa + 16384 + sw,
                           Bt + (size_t)(cbase + row) * K + s * 64 + c * 8);
            }
        }
        CP_COMMIT();
    }

    for (int kc = 0; kc < nk; kc++) {
        CP_WAIT2();
        __syncthreads();
        const uint32_t sa = sb + (kc % 3) * STAGE_BYTES;
        const uint32_t sbB = sa + 16384;
#pragma unroll
        for (int ks = 0; ks < 4; ks++) {
            uint32_t a[4][4], b[2][4];
#pragma unroll
            for (int mi = 0; mi < 4; mi++)
                ldmx4(a[mi], sa + sw128(aBase + mi * 2048 + ks * 32));
#pragma unroll
            for (int g = 0; g < 2; g++)
                ldmx4(b[g], sbB + sw128(bBase + g * 2048 + ks * 32));
#pragma unroll
            for (int mi = 0; mi < 4; mi++)
#pragma unroll
                for (int nj = 0; nj < 4; nj++)
                    mma_bf16(acc[mi][nj], a[mi],
                             b[nj >> 1][(nj & 1) * 2], b[nj >> 1][(nj & 1) * 2 + 1]);
        }
        __syncthreads();
        const int nx = kc + 3;
        if (nx < nk) {
            const uint32_t sn = sb + (nx % 3) * STAGE_BYTES;
#pragma unroll
            for (int i = 0; i < 4; i++) {
                int id = ldid0 + i * 256;
                int row = id >> 3, c = id & 7;
                uint32_t sw = sw128(row * 128 + c * 16);
                CP_ASYNC16(sn + sw,
                           A + (size_t)(rb + row) * K + nx * 64 + c * 8);
                CP_ASYNC16(sn + 16384 + sw,
                           Bt + (size_t)(cbase + row) * K + nx * 64 + c * 8);
            }
        }
        CP_COMMIT();
    }

    // ---- epilogue
    const int er0 = wm * 64 + (lane >> 2);
    const int ec0 = wn * 32 + (lane & 3) * 2;
    float lsum = 0.f;
#pragma unroll
    for (int mi = 0; mi < 4; mi++) {
#pragma unroll
        for (int half = 0; half < 2; half++) {
            const int r = rb + er0 + mi * 16 + half * 8;
#pragma unroll
            for (int nj = 0; nj < 4; nj++) {
                const int cc = cbase + ec0 + nj * 8;
                float v0 = acc[mi][nj][half * 2];
                float v1 = acc[mi][nj][half * 2 + 1];
                if (EPI == 1) {
                    v0 = fmaxf(v0 + bias[cc], 0.f);
                    v1 = fmaxf(v1 + bias[cc + 1], 0.f);
                    *(__nv_bfloat162*)(Cb + (size_t)r * N + cc) =
                        __floats2bfloat162_rn(v0, v1);
                } else if (EPI == 3) {
                    Cf[(size_t)r * N + cc]     = v0 + bias[cc];
                    Cf[(size_t)r * N + cc + 1] = v1 + bias[cc + 1];
                } else if (EPI == 4) {
                    const __nv_bfloat16* mr = maskp + (size_t)(r >> 5) * N + cc;
                    v0 = (__bfloat162float(mr[0]) > 0.f) ? v0 : 0.f;
                    v1 = (__bfloat162float(mr[1]) > 0.f) ? v1 : 0.f;
                    *(__nv_bfloat162*)(Cb + (size_t)r * N + cc) =
                        __floats2bfloat162_rn(v0, v1);
                } else {   // EPI 5: fused weighted squared error
                    const float* xr = xnn   + (size_t)r * N + cc;
                    const float* rr = recon + (size_t)(r >> 5) * N + cc;
                    float e0 = xr[0] - rr[0] - v0;
                    float e1 = xr[1] - rr[1] - v1;
                    lsum += wrow[r] * (e0 * e0 + e1 * e1);
                }
            }
        }
    }
    if (EPI == 5) {
#pragma unroll
        for (int o = 16; o; o >>= 1) lsum += __shfl_down_sync(0xffffffffu, lsum, o);
        __shared__ float red[8];
        if ((tid & 31) == 0) red[wid] = lsum;
        __syncthreads();
        if (tid == 0) {
            float t = 0.f;
#pragma unroll
            for (int i = 0; i < 8; i++) t += red[i];
            lpart[blockIdx.y * gridDim.x + blockIdx.x] = t;
        }
    }
}

// ---------------------------------------------------------------------------
// Conversions & small kernels
// ---------------------------------------------------------------------------
__global__ void conv_x(const float* __restrict__ xc, const float* __restrict__ xnn)
{
    size_t i = (size_t)blockIdx.x * 256 + threadIdx.x;   // float4 index
    const size_t nC = (size_t)BS_ * D_ / 4;
    float4 v = (i < nC) ? ((const float4*)xc)[i] : ((const float4*)xnn)[i - nC];
    __nv_bfloat162* o = (__nv_bfloat162*)g_xa + i * 2;
    o[0] = __floats2bfloat162_rn(v.x, v.y);
    o[1] = __floats2bfloat162_rn(v.z, v.w);
}

// W[K,N] f32 -> Wt[N,Kp] bf16 (zero pad K..Kp)
__global__ void __launch_bounds__(256) transpose_bf16(
    const float* __restrict__ in, __nv_bfloat16* __restrict__ out,
    int K, int N, int Kp)
{
    __shared__ float tile[32][33];
    const int kb = blockIdx.y * 32, nb = blockIdx.x * 32;
    const int tx = threadIdx.x & 31, ty = threadIdx.x >> 5;
#pragma unroll
    for (int i = 0; i < 32; i += 8) {
        int k = kb + ty + i, n = nb + tx;
        tile[ty + i][tx] = (k < K && n < N) ? in[(size_t)k * N + n] : 0.f;
    }
    __syncthreads();
#pragma unroll
    for (int i = 0; i < 32; i += 8) {
        int n = nb + ty + i, k = kb + tx;
        out[(size_t)n * Kp + k] = __float2bfloat16(tile[tx][ty + i]);
    }
}

// zcb [128x64] and dzb [4096x64] (padded bf16) from g_z32
__global__ void conv_z()
{
    const int i = blockIdx.x * 256 + threadIdx.x;
    if (i < BS_ * 64) {
        int r = i >> 6, c = i & 63;
        g_zcb[i] = __float2bfloat16(c < 32 ? g_z32[r * 32 + c] : 0.f);
    } else {
        int j = i - BS_ * 64;
        int r = j >> 6, c = j & 63;
        float v = (c < 32) ? g_z32[(BS_ + r) * 32 + c] - g_z32[(r >> 5) * 32 + c] : 0.f;
        g_dzb[j] = __float2bfloat16(v);
    }
}

// z = h2b(bf16) @ We3(f32) + be3 ; 64 rows/block, 8 accs/thread
__global__ void __launch_bounds__(256) fc_skinny(
    const __nv_bfloat16* __restrict__ A, const float* __restrict__ B,
    const float* __restrict__ bias, float* __restrict__ C)
{
    __shared__ float As[64][128];
    const int r0 = blockIdx.x * 64;
    const int c = threadIdx.x & 31, rg = threadIdx.x >> 5;
    float acc[8] = {};
    for (int kt = 0; kt < H_; kt += 128) {
        __syncthreads();
        for (int l = threadIdx.x; l < 64 * 64; l += 256) {
            int rr = l >> 6, cc2 = l & 63;
            __nv_bfloat162 v =
                *((const __nv_bfloat162*)(A + (size_t)(r0 + rr) * H_ + kt) + cc2);
            *(float2*)&As[rr][cc2 * 2] =
                make_float2(__bfloat162float(v.x), __bfloat162float(v.y));
        }
        __syncthreads();
        for (int k = 0; k < 128; k++) {
            float b = B[(size_t)(kt + k) * 32 + c];
#pragma unroll
            for (int i = 0; i < 8; i++) acc[i] += As[rg * 8 + i][k] * b;
        }
    }
    const float bs = bias[c];
#pragma unroll
    for (int i = 0; i < 8; i++)
        C[(size_t)(r0 + rg * 8 + i) * 32 + c] = acc[i] + bs;
}

__global__ void __launch_bounds__(128) weights_kernel(
    const float* __restrict__ xc, const float* __restrict__ xnn)
{
    const int rowi = blockIdx.x;
    const float4* a = (const float4*)(xc + (size_t)(rowi >> 5) * D_);
    const float4* x = (const float4*)(xnn + (size_t)rowi * D_);
    float s = 0.f;
    for (int d = threadIdx.x; d < D_ / 4; d += 128) {
        float4 av = a[d], xv = x[d];
        float dx = av.x - xv.x, dy = av.y - xv.y, dz2 = av.z - xv.z, dw = av.w - xv.w;
        s += dx * dx + dy * dy + dz2 * dz2 + dw * dw;
    }
#pragma unroll
    for (int o = 16; o; o >>= 1) s += __shfl_down_sync(0xffffffffu, s, o);
    __shared__ float red[4];
    if ((threadIdx.x & 31) == 0) red[threadIdx.x >> 5] = s;
    __syncthreads();
    if (threadIdx.x == 0)
        g_w[rowi] = (red[0] + red[1] + red[2] + red[3] > 1e-24f) ? 1.0f : 0.5f;
}

__global__ void final_reduce(float* __restrict__ out)
{
    float s = 0.f;
    for (int i = threadIdx.x; i < 768; i += 256) s += g_lpart[i];
#pragma unroll
    for (int o = 16; o; o >>= 1) s += __shfl_down_sync(0xffffffffu, s, o);
    __shared__ float red[8];
    if ((threadIdx.x & 31) == 0) red[threadIdx.x >> 5] = s;
    __syncthreads();
    if (threadIdx.x == 0) {
        float t = 0.f;
#pragma unroll
        for (int i = 0; i < 8; i++) t += red[i];
        out[0] = t * (1.0f / (float)(BS_ * NN_));
    }
}

// ---------------------------------------------------------------------------
extern "C" void kernel_launch(void* const* d_in, const int* in_sizes, int n_in,
                              void* d_out, int out_size)
{
    const float* x_c = (const float*)d_in[0];
    const float* x_nn = (const float*)d_in[1];
    const float* We1 = (const float*)d_in[2];
    const float* be1 = (const float*)d_in[3];
    const float* We2 = (const float*)d_in[4];
    const float* be2 = (const float*)d_in[5];
    const float* We3 = (const float*)d_in[6];
    const float* be3 = (const float*)d_in[7];
    const float* Wd1 = (const float*)d_in[8];
    const float* bd1 = (const float*)d_in[9];
    const float* Wd2 = (const float*)d_in[10];
    const float* bd2 = (const float*)d_in[11];
    const float* Wd3 = (const float*)d_in[12];
    const float* bd3 = (const float*)d_in[13];
    float* out = (float*)d_out;

    cudaFuncSetAttribute(tgemm<1>, cudaFuncAttributeMaxDynamicSharedMemorySize, SMEM_BYTES);
    cudaFuncSetAttribute(tgemm<3>, cudaFuncAttributeMaxDynamicSharedMemorySize, SMEM_BYTES);
    cudaFuncSetAttribute(tgemm<4>, cudaFuncAttributeMaxDynamicSharedMemorySize, SMEM_BYTES);
    cudaFuncSetAttribute(tgemm<5>, cudaFuncAttributeMaxDynamicSharedMemorySize, SMEM_BYTES);

    __nv_bfloat16 *xa, *h1b, *h2b, *We1t, *We2t, *Wd1t, *Wd2t, *Wd3t, *zcb, *dzb, *h1cb, *h2cb;
    float *z32, *recon, *w, *lpart;
    cudaGetSymbolAddress((void**)&xa, g_xa);
    cudaGetSymbolAddress((void**)&h1b, g_h1b);
    cudaGetSymbolAddress((void**)&h2b, g_h2b);
    cudaGetSymbolAddress((void**)&We1t, g_We1t);
    cudaGetSymbolAddress((void**)&We2t, g_We2t);
    cudaGetSymbolAddress((void**)&Wd1t, g_Wd1t);
    cudaGetSymbolAddress((void**)&Wd2t, g_Wd2t);
    cudaGetSymbolAddress((void**)&Wd3t, g_Wd3t);
    cudaGetSymbolAddress((void**)&zcb, g_zcb);
    cudaGetSymbolAddress((void**)&dzb, g_dzb);
    cudaGetSymbolAddress((void**)&h1cb, g_h1cb);
    cudaGetSymbolAddress((void**)&h2cb, g_h2cb);
    cudaGetSymbolAddress((void**)&z32, g_z32);
    cudaGetSymbolAddress((void**)&recon, g_recon);
    cudaGetSymbolAddress((void**)&w, g_w);
    cudaGetSymbolAddress((void**)&lpart, g_lpart);

    // bf16 conversions / weight transposes
    conv_x<<<(MALL * D_ / 4) / 256, 256>>>(x_c, x_nn);
    transpose_bf16<<<dim3(32, 96), 256>>>(We1, We1t, D_, H_, D_);
    transpose_bf16<<<dim3(32, 32), 256>>>(We2, We2t, H_, H_, H_);
    transpose_bf16<<<dim3(32, 2),  256>>>(Wd1, Wd1t, Z_, H_, 64);
    transpose_bf16<<<dim3(32, 32), 256>>>(Wd2, Wd2t, H_, H_, H_);
    transpose_bf16<<<dim3(96, 32), 256>>>(Wd3, Wd3t, H_, D_, H_);
    weights_kernel<<<MNN, 128>>>(x_c, x_nn);

    const dim3 t(256);
    // Encoder (all 4224 rows at once)
    tgemm<1><<<dim3(8, 33), t, SMEM_BYTES>>>(xa, We1t, D_, H_, h1b, nullptr,
        be1, nullptr, nullptr, nullptr, nullptr, nullptr);
    tgemm<1><<<dim3(8, 33), t, SMEM_BYTES>>>(h1b, We2t, H_, H_, h2b, nullptr,
        be2, nullptr, nullptr, nullptr, nullptr, nullptr);
    fc_skinny<<<MALL / 64, 256>>>(h2b, We3, be3, z32);
    conv_z<<<(BS_ * 64 + MNN * 64) / 256, 256>>>();

    // Center decoder (relu'd activations double as JVP masks)
    tgemm<1><<<dim3(8, 1), t, SMEM_BYTES>>>(zcb, Wd1t, 64, H_, h1cb, nullptr,
        bd1, nullptr, nullptr, nullptr, nullptr, nullptr);
    tgemm<1><<<dim3(8, 1), t, SMEM_BYTES>>>(h1cb, Wd2t, H_, H_, h2cb, nullptr,
        bd2, nullptr, nullptr, nullptr, nullptr, nullptr);
    tgemm<3><<<dim3(24, 1), t, SMEM_BYTES>>>(h2cb, Wd3t, H_, D_, nullptr, recon,
        bd3, nullptr, nullptr, nullptr, nullptr, nullptr);

    // JVP chain (hessian term is exactly 0 for ReLU decoder)
    tgemm<4><<<dim3(8, 32), t, SMEM_BYTES>>>(dzb, Wd1t, 64, H_, h1b, nullptr,
        nullptr, h1cb, nullptr, nullptr, nullptr, nullptr);
    tgemm<4><<<dim3(8, 32), t, SMEM_BYTES>>>(h1b, Wd2t, H_, H_, h2b, nullptr,
        nullptr, h2cb, nullptr, nullptr, nullptr, nullptr);

    // Final GEMM with fused weighted squared-error loss
    tgemm<5><<<dim3(24, 32), t, SMEM_BYTES>>>(h2b, Wd3t, H_, D_, nullptr, nullptr,
        nullptr, nullptr, x_nn, recon, w, lpart);
    final_reduce<<<1, 256>>>(out);
}

// round 8
// speedup vs baseline: 6.2461x; 1.0161x over previous
#include <cuda_runtime.h>
#include <cuda_bf16.h>
#include <cstdint>

#define D_   3072
#define H_   1024
#define Z_   32
#define BS_  128
#define NN_  32
#define MNN  4096   // BS_*NN_
#define MALL 4224   // BS_ + MNN

// ---------------------------------------------------------------------------
// Static scratch (allocation-free rule)
// ---------------------------------------------------------------------------
__device__ __align__(16) __nv_bfloat16 g_xa[MALL * D_];    // [x_c; x_nn] bf16
__device__ __align__(16) __nv_bfloat16 g_h1b[MALL * H_];   // enc h1 / jvp t1
__device__ __align__(16) __nv_bfloat16 g_h2b[MALL * H_];   // enc h2 / jvp t2
__device__ __align__(16) __nv_bfloat16 g_We1t[H_ * D_];    // We1^T [N,K] bf16
__device__ __align__(16) __nv_bfloat16 g_We2t[H_ * H_];
__device__ __align__(16) __nv_bfloat16 g_Wd1t[H_ * 64];    // Wd1^T, K pad 32->64
__device__ __align__(16) __nv_bfloat16 g_Wd2t[H_ * H_];
__device__ __align__(16) __nv_bfloat16 g_Wd3t[D_ * H_];
__device__ __align__(16) __nv_bfloat16 g_zcb[BS_ * 64];    // z_c bf16, padded
__device__ __align__(16) __nv_bfloat16 g_dzb[MNN * 64];    // dz bf16, padded
__device__ __align__(16) __nv_bfloat16 g_h1cb[BS_ * H_];   // center dec h1 (mask1)
__device__ __align__(16) __nv_bfloat16 g_h2cb[BS_ * H_];   // center dec h2 (mask2)
__device__ float g_z32[MALL * Z_];
__device__ float g_recon[BS_ * D_];
__device__ float g_w[MNN];
__device__ float g_lpart[768];

// ---------------------------------------------------------------------------
// PTX helpers (plain sm_80+ PTX — assembles for target sm_103)
// ---------------------------------------------------------------------------
__device__ __forceinline__ uint32_t smem_u32(const void* p)
{
    uint32_t a;
    asm("{ .reg .u64 t; cvta.to.shared.u64 t, %1; cvt.u32.u64 %0, t; }"
        : "=r"(a) : "l"(p));
    return a;
}
#define CP_ASYNC16(dst, src) \
    asm volatile("cp.async.cg.shared.global [%0], [%1], 16;" \
                 :: "r"(dst), "l"(src) : "memory")
#define CP_COMMIT()  asm volatile("cp.async.commit_group;" ::: "memory")
#define CP_WAIT1()   asm volatile("cp.async.wait_group 1;" ::: "memory")

__device__ __forceinline__ void ldmx4(uint32_t* r, uint32_t addr)
{
    asm volatile("ldmatrix.sync.aligned.m8n8.x4.shared.b16 {%0,%1,%2,%3}, [%4];"
                 : "=r"(r[0]), "=r"(r[1]), "=r"(r[2]), "=r"(r[3]) : "r"(addr));
}
__device__ __forceinline__ void mma_bf16(float* c, const uint32_t* a,
                                         uint32_t b0, uint32_t b1)
{
    asm volatile(
        "mma.sync.aligned.m16n8k16.row.col.f32.bf16.bf16.f32 "
        "{%0,%1,%2,%3}, {%4,%5,%6,%7}, {%8,%9}, {%0,%1,%2,%3};"
        : "+f"(c[0]), "+f"(c[1]), "+f"(c[2]), "+f"(c[3])
        : "r"(a[0]), "r"(a[1]), "r"(a[2]), "r"(a[3]), "r"(b0), "r"(b1));
}
__device__ __forceinline__ uint32_t sw128(uint32_t o) { return o ^ ((o >> 3) & 0x70); }

// ---------------------------------------------------------------------------
// Warp-MMA GEMM: C[M,N] = A[M,K] @ Bt[N,K]^T  (bf16 in, fp32 accum)
// Block 128x128, BK=64, 8 warps (2x4), warp tile 64x32.
// 3-stage cp.async with prefetch distance 2: ONE barrier per K-chunk,
// loads for stage kc+2 issued before compute on stage kc.
// EPI: 1 bias+relu->bf16 | 3 bias->f32 | 4 mask(bf16>0)->bf16 | 5 fused loss
// ---------------------------------------------------------------------------
static constexpr int STAGE_BYTES = 32768;           // A 16KB + B 16KB
static constexpr int SMEM_BYTES  = 3 * STAGE_BYTES; // 96KB -> 2 CTAs/SM

template <int EPI>
__global__ void __launch_bounds__(256, 2) tgemm(
    const __nv_bfloat16* __restrict__ A, const __nv_bfloat16* __restrict__ Bt,
    int K, int N,
    __nv_bfloat16* __restrict__ Cb, float* __restrict__ Cf,
    const float* __restrict__ bias, const __nv_bfloat16* __restrict__ maskp,
    const float* __restrict__ xnn, const float* __restrict__ recon,
    const float* __restrict__ wrow, float* __restrict__ lpart)
{
    extern __shared__ __align__(128) char smem[];
    const uint32_t sb = smem_u32(smem);
    const int tid = threadIdx.x, lane = tid & 31, wid = tid >> 5;
    const int wm = wid & 1, wn = wid >> 1;           // 2 x 4 warp grid
    const int rb = blockIdx.y << 7, cbase = blockIdx.x << 7;

    float acc[4][4][4];
#pragma unroll
    for (int i = 0; i < 4; i++)
#pragma unroll
        for (int j = 0; j < 4; j++)
#pragma unroll
            for (int q = 0; q < 4; q++) acc[i][j][q] = 0.f;

    const int nk = K >> 6;

    // per-thread cp.async mapping: 4 x 16B for A + 4 x 16B for B per stage
    const int ldrow = tid >> 3;           // +32 per i
    const int ldc   = tid & 7;
    const uint32_t swb = sw128(ldrow * 128 + ldc * 16);
    const __nv_bfloat16* Abase = A  + (size_t)(rb + ldrow) * K + ldc * 8;
    const __nv_bfloat16* Bbase = Bt + (size_t)(cbase + ldrow) * K + ldc * 8;

    // ldmatrix base offsets (bytes within a 128-row x 128B stage tile)
    const int aBase = (wm * 64 + (lane & 15)) * 128 + ((lane >> 4) * 16);
    const int bBase = (wn * 32 + (lane & 7) + ((lane >> 4) * 8)) * 128
                    + (((lane >> 3) & 1) * 16);

    // ---- prologue: fill 2 stages (prefetch distance 2)
#pragma unroll
    for (int s = 0; s < 2; s++) {
        if (s < nk) {
            const uint32_t sa = sb + s * STAGE_BYTES;
#pragma unroll
            for (int i = 0; i < 4; i++) {
                uint32_t sw = sw128((ldrow + i * 32) * 128 + ldc * 16);
                CP_ASYNC16(sa + sw,        Abase + (size_t)(i * 32) * K + s * 64);
                CP_ASYNC16(sa + 16384 + sw, Bbase + (size_t)(i * 32) * K + s * 64);
            }
        }
        CP_COMMIT();
    }

    for (int kc = 0; kc < nk; kc++) {
        CP_WAIT1();            // groups retire in order => stage kc resident
        __syncthreads();       // all warps done with stage (kc-1)%3 too

        // issue stage kc+2 into buffer (kc+2)%3 (free since last iteration)
        const int nx = kc + 2;
        if (nx < nk) {
            const uint32_t sn = sb + (nx % 3) * STAGE_BYTES;
#pragma unroll
            for (int i = 0; i < 4; i++) {
                uint32_t sw = sw128((ldrow + i * 32) * 128 + ldc * 16);
                CP_ASYNC16(sn + sw,        Abase + (size_t)(i * 32) * K + nx * 64);
                CP_ASYNC16(sn + 16384 + sw, Bbase + (size_t)(i * 32) * K + nx * 64);
            }
        }
        CP_COMMIT();

        const uint32_t sa = sb + (kc % 3) * STAGE_BYTES;
        const uint32_t sbB = sa + 16384;
#pragma unroll
        for (int ks = 0; ks < 4; ks++) {
            uint32_t a[4][4], b[2][4];
#pragma unroll
            for (int mi = 0; mi < 4; mi++)
                ldmx4(a[mi], sa + sw128(aBase + mi * 2048 + ks * 32));
#pragma unroll
            for (int g = 0; g < 2; g++)
                ldmx4(b[g], sbB + sw128(bBase + g * 2048 + ks * 32));
#pragma unroll
            for (int mi = 0; mi < 4; mi++)
#pragma unroll
                for (int nj = 0; nj < 4; nj++)
                    mma_bf16(acc[mi][nj], a[mi],
                             b[nj >> 1][(nj & 1) * 2], b[nj >> 1][(nj & 1) * 2 + 1]);
        }
    }

    // ---- epilogue
    const int er0 = wm * 64 + (lane >> 2);
    const int ec0 = wn * 32 + (lane & 3) * 2;
    float lsum = 0.f;
#pragma unroll
    for (int mi = 0; mi < 4; mi++) {
#pragma unroll
        for (int half = 0; half < 2; half++) {
            const int r = rb + er0 + mi * 16 + half * 8;
#pragma unroll
            for (int nj = 0; nj < 4; nj++) {
                const int cc = cbase + ec0 + nj * 8;
                float v0 = acc[mi][nj][half * 2];
                float v1 = acc[mi][nj][half * 2 + 1];
                if (EPI == 1) {
                    v0 = fmaxf(v0 + bias[cc], 0.f);
                    v1 = fmaxf(v1 + bias[cc + 1], 0.f);
                    *(__nv_bfloat162*)(Cb + (size_t)r * N + cc) =
                        __floats2bfloat162_rn(v0, v1);
                } else if (EPI == 3) {
                    Cf[(size_t)r * N + cc]     = v0 + bias[cc];
                    Cf[(size_t)r * N + cc + 1] = v1 + bias[cc + 1];
                } else if (EPI == 4) {
                    const __nv_bfloat16* mr = maskp + (size_t)(r >> 5) * N + cc;
                    v0 = (__bfloat162float(mr[0]) > 0.f) ? v0 : 0.f;
                    v1 = (__bfloat162float(mr[1]) > 0.f) ? v1 : 0.f;
                    *(__nv_bfloat162*)(Cb + (size_t)r * N + cc) =
                        __floats2bfloat162_rn(v0, v1);
                } else {   // EPI 5: fused weighted squared error
                    const float* xr = xnn   + (size_t)r * N + cc;
                    const float* rr = recon + (size_t)(r >> 5) * N + cc;
                    float e0 = xr[0] - rr[0] - v0;
                    float e1 = xr[1] - rr[1] - v1;
                    lsum += wrow[r] * (e0 * e0 + e1 * e1);
                }
            }
        }
    }
    if (EPI == 5) {
#pragma unroll
        for (int o = 16; o; o >>= 1) lsum += __shfl_down_sync(0xffffffffu, lsum, o);
        __shared__ float red[8];
        if ((tid & 31) == 0) red[wid] = lsum;
        __syncthreads();
        if (tid == 0) {
            float t = 0.f;
#pragma unroll
            for (int i = 0; i < 8; i++) t += red[i];
            lpart[blockIdx.y * gridDim.x + blockIdx.x] = t;
        }
    }
}

// ---------------------------------------------------------------------------
// Fused conversion + binary-kernel weights.
// One block per row of [x_c; x_nn]: convert row to bf16; for neighbor rows
// also reduce ||x_c[b]-x_nn[b,n]||^2 and write g_w.
// ---------------------------------------------------------------------------
__global__ void __launch_bounds__(256) conv_x_w(
    const float* __restrict__ xc, const float* __restrict__ xnn)
{
    const int r = blockIdx.x;
    if (r < BS_) {
        const float4* src = (const float4*)(xc + (size_t)r * D_);
        __nv_bfloat162* dst = (__nv_bfloat162*)(g_xa + (size_t)r * D_);
#pragma unroll
        for (int i = 0; i < 3; i++) {
            float4 v = src[threadIdx.x + i * 256];
            dst[(threadIdx.x + i * 256) * 2]     = __floats2bfloat162_rn(v.x, v.y);
            dst[(threadIdx.x + i * 256) * 2 + 1] = __floats2bfloat162_rn(v.z, v.w);
        }
        return;
    }
    const int rn = r - BS_;
    const float4* src = (const float4*)(xnn + (size_t)rn * D_);
    const float4* cen = (const float4*)(xc + (size_t)(rn >> 5) * D_);
    __nv_bfloat162* dst = (__nv_bfloat162*)(g_xa + (size_t)r * D_);
    float s = 0.f;
#pragma unroll
    for (int i = 0; i < 3; i++) {
        float4 v = src[threadIdx.x + i * 256];
        float4 c = cen[threadIdx.x + i * 256];
        dst[(threadIdx.x + i * 256) * 2]     = __floats2bfloat162_rn(v.x, v.y);
        dst[(threadIdx.x + i * 256) * 2 + 1] = __floats2bfloat162_rn(v.z, v.w);
        float dx = v.x - c.x, dy = v.y - c.y, dz2 = v.z - c.z, dw = v.w - c.w;
        s += dx * dx + dy * dy + dz2 * dz2 + dw * dw;
    }
#pragma unroll
    for (int o = 16; o; o >>= 1) s += __shfl_down_sync(0xffffffffu, s, o);
    __shared__ float red[8];
    if ((threadIdx.x & 31) == 0) red[threadIdx.x >> 5] = s;
    __syncthreads();
    if (threadIdx.x == 0) {
        float t = 0.f;
#pragma unroll
        for (int i = 0; i < 8; i++) t += red[i];
        g_w[rn] = (t > 1e-24f) ? 1.0f : 0.5f;   // dist > 1e-12 <=> dist^2 > 1e-24
    }
}

// W[K,N] f32 -> Wt[N,Kp] bf16 (zero pad K..Kp)
__global__ void __launch_bounds__(256) transpose_bf16(
    const float* __restrict__ in, __nv_bfloat16* __restrict__ out,
    int K, int N, int Kp)
{
    __shared__ float tile[32][33];
    const int kb = blockIdx.y * 32, nb = blockIdx.x * 32;
    const int tx = threadIdx.x & 31, ty = threadIdx.x >> 5;
#pragma unroll
    for (int i = 0; i < 32; i += 8) {
        int k = kb + ty + i, n = nb + tx;
        tile[ty + i][tx] = (k < K && n < N) ? in[(size_t)k * N + n] : 0.f;
    }
    __syncthreads();
#pragma unroll
    for (int i = 0; i < 32; i += 8) {
        int n = nb + ty + i, k = kb + tx;
        out[(size_t)n * Kp + k] = __float2bfloat16(tile[tx][ty + i]);
    }
}

// zcb [128x64] and dzb [4096x64] (padded bf16) from g_z32
__global__ void conv_z()
{
    const int i = blockIdx.x * 256 + threadIdx.x;
    if (i < BS_ * 64) {
        int r = i >> 6, c = i & 63;
        g_zcb[i] = __float2bfloat16(c < 32 ? g_z32[r * 32 + c] : 0.f);
    } else {
        int j = i - BS_ * 64;
        int r = j >> 6, c = j & 63;
        float v = (c < 32) ? g_z32[(BS_ + r) * 32 + c] - g_z32[(r >> 5) * 32 + c] : 0.f;
        g_dzb[j] = __float2bfloat16(v);
    }
}

// z = h2b(bf16) @ We3(f32) + be3 ; 64 rows/block, 8 accs/thread
__global__ void __launch_bounds__(256) fc_skinny(
    const __nv_bfloat16* __restrict__ A, const float* __restrict__ B,
    const float* __restrict__ bias, float* __restrict__ C)
{
    __shared__ float As[64][128];
    const int r0 = blockIdx.x * 64;
    const int c = threadIdx.x & 31, rg = threadIdx.x >> 5;
    float acc[8] = {};
    for (int kt = 0; kt < H_; kt += 128) {
        __syncthreads();
        for (int l = threadIdx.x; l < 64 * 64; l += 256) {
            int rr = l >> 6, cc2 = l & 63;
            __nv_bfloat162 v =
                *((const __nv_bfloat162*)(A + (size_t)(r0 + rr) * H_ + kt) + cc2);
            *(float2*)&As[rr][cc2 * 2] =
                make_float2(__bfloat162float(v.x), __bfloat162float(v.y));
        }
        __syncthreads();
        for (int k = 0; k < 128; k++) {
            float b = B[(size_t)(kt + k) * 32 + c];
#pragma unroll
            for (int i = 0; i < 8; i++) acc[i] += As[rg * 8 + i][k] * b;
        }
    }
    const float bs = bias[c];
#pragma unroll
    for (int i = 0; i < 8; i++)
        C[(size_t)(r0 + rg * 8 + i) * 32 + c] = acc[i] + bs;
}

__global__ void final_reduce(float* __restrict__ out)
{
    float s = 0.f;
    for (int i = threadIdx.x; i < 768; i += 256) s += g_lpart[i];
#pragma unroll
    for (int o = 16; o; o >>= 1) s += __shfl_down_sync(0xffffffffu, s, o);
    __shared__ float red[8];
    if ((threadIdx.x & 31) == 0) red[threadIdx.x >> 5] = s;
    __syncthreads();
    if (threadIdx.x == 0) {
        float t = 0.f;
#pragma unroll
        for (int i = 0; i < 8; i++) t += red[i];
        out[0] = t * (1.0f / (float)(BS_ * NN_));
    }
}

// ---------------------------------------------------------------------------
extern "C" void kernel_launch(void* const* d_in, const int* in_sizes, int n_in,
                              void* d_out, int out_size)
{
    const float* x_c = (const float*)d_in[0];
    const float* x_nn = (const float*)d_in[1];
    const float* We1 = (const float*)d_in[2];
    const float* be1 = (const float*)d_in[3];
    const float* We2 = (const float*)d_in[4];
    const float* be2 = (const float*)d_in[5];
    const float* We3 = (const float*)d_in[6];
    const float* be3 = (const float*)d_in[7];
    const float* Wd1 = (const float*)d_in[8];
    const float* bd1 = (const float*)d_in[9];
    const float* Wd2 = (const float*)d_in[10];
    const float* bd2 = (const float*)d_in[11];
    const float* Wd3 = (const float*)d_in[12];
    const float* bd3 = (const float*)d_in[13];
    float* out = (float*)d_out;

    cudaFuncSetAttribute(tgemm<1>, cudaFuncAttributeMaxDynamicSharedMemorySize, SMEM_BYTES);
    cudaFuncSetAttribute(tgemm<3>, cudaFuncAttributeMaxDynamicSharedMemorySize, SMEM_BYTES);
    cudaFuncSetAttribute(tgemm<4>, cudaFuncAttributeMaxDynamicSharedMemorySize, SMEM_BYTES);
    cudaFuncSetAttribute(tgemm<5>, cudaFuncAttributeMaxDynamicSharedMemorySize, SMEM_BYTES);

    __nv_bfloat16 *xa, *h1b, *h2b, *We1t, *We2t, *Wd1t, *Wd2t, *Wd3t, *zcb, *dzb, *h1cb, *h2cb;
    float *z32, *recon, *w, *lpart;
    cudaGetSymbolAddress((void**)&xa, g_xa);
    cudaGetSymbolAddress((void**)&h1b, g_h1b);
    cudaGetSymbolAddress((void**)&h2b, g_h2b);
    cudaGetSymbolAddress((void**)&We1t, g_We1t);
    cudaGetSymbolAddress((void**)&We2t, g_We2t);
    cudaGetSymbolAddress((void**)&Wd1t, g_Wd1t);
    cudaGetSymbolAddress((void**)&Wd2t, g_Wd2t);
    cudaGetSymbolAddress((void**)&Wd3t, g_Wd3t);
    cudaGetSymbolAddress((void**)&zcb, g_zcb);
    cudaGetSymbolAddress((void**)&dzb, g_dzb);
    cudaGetSymbolAddress((void**)&h1cb, g_h1cb);
    cudaGetSymbolAddress((void**)&h2cb, g_h2cb);
    cudaGetSymbolAddress((void**)&z32, g_z32);
    cudaGetSymbolAddress((void**)&recon, g_recon);
    cudaGetSymbolAddress((void**)&w, g_w);
    cudaGetSymbolAddress((void**)&lpart, g_lpart);

    // conversions + weights (fused) and weight transposes
    conv_x_w<<<MALL, 256>>>(x_c, x_nn);
    transpose_bf16<<<dim3(32, 96), 256>>>(We1, We1t, D_, H_, D_);
    transpose_bf16<<<dim3(32, 32), 256>>>(We2, We2t, H_, H_, H_);
    transpose_bf16<<<dim3(32, 2),  256>>>(Wd1, Wd1t, Z_, H_, 64);
    transpose_bf16<<<dim3(32, 32), 256>>>(Wd2, Wd2t, H_, H_, H_);
    transpose_bf16<<<dim3(96, 32), 256>>>(Wd3, Wd3t, H_, D_, H_);

    const dim3 t(256);
    // Encoder (all 4224 rows at once)
    tgemm<1><<<dim3(8, 33), t, SMEM_BYTES>>>(xa, We1t, D_, H_, h1b, nullptr,
        be1, nullptr, nullptr, nullptr, nullptr, nullptr);
    tgemm<1><<<dim3(8, 33), t, SMEM_BYTES>>>(h1b, We2t, H_, H_, h2b, nullptr,
        be2, nullptr, nullptr, nullptr, nullptr, nullptr);
    fc_skinny<<<MALL / 64, 256>>>(h2b, We3, be3, z32);
    conv_z<<<(BS_ * 64 + MNN * 64) / 256, 256>>>();

    // Center decoder (relu'd activations double as JVP masks)
    tgemm<1><<<dim3(8, 1), t, SMEM_BYTES>>>(zcb, Wd1t, 64, H_, h1cb, nullptr,
        bd1, nullptr, nullptr, nullptr, nullptr, nullptr);
    tgemm<1><<<dim3(8, 1), t, SMEM_BYTES>>>(h1cb, Wd2t, H_, H_, h2cb, nullptr,
        bd2, nullptr, nullptr, nullptr, nullptr, nullptr);
    tgemm<3><<<dim3(24, 1), t, SMEM_BYTES>>>(h2cb, Wd3t, H_, D_, nullptr, recon,
        bd3, nullptr, nullptr, nullptr, nullptr, nullptr);

    // JVP chain (hessian term is exactly 0 for ReLU decoder)
    tgemm<4><<<dim3(8, 32), t, SMEM_BYTES>>>(dzb, Wd1t, 64, H_, h1b, nullptr,
        nullptr, h1cb, nullptr, nullptr, nullptr, nullptr);
    tgemm<4><<<dim3(8, 32), t, SMEM_BYTES>>>(h1b, Wd2t, H_, H_, h2b, nullptr,
        nullptr, h2cb, nullptr, nullptr, nullptr, nullptr);

    // Final GEMM with fused weighted squared-error loss
    tgemm<5><<<dim3(24, 32), t, SMEM_BYTES>>>(h2b, Wd3t, H_, D_, nullptr, nullptr,
        nullptr, nullptr, x_nn, recon, w, lpart);
    final_reduce<<<1, 256>>>(out);
}

// round 9
// speedup vs baseline: 6.5999x; 1.0566x over previous
#include <cuda_runtime.h>
#include <cuda_bf16.h>
#include <cstdint>

#define D_   3072
#define H_   1024
#define Z_   32
#define BS_  128
#define NN_  32
#define MNN  4096   // BS_*NN_
#define MALL 4224   // BS_ + MNN

// ---------------------------------------------------------------------------
// Static scratch (allocation-free rule)
// ---------------------------------------------------------------------------
__device__ __align__(16) __nv_bfloat16 g_xa[MALL * D_];    // [x_c; x_nn] bf16
__device__ __align__(16) __nv_bfloat16 g_h1b[MALL * H_];   // enc h1 / jvp t1
__device__ __align__(16) __nv_bfloat16 g_h2b[MALL * H_];   // enc h2 / jvp t2
__device__ __align__(16) __nv_bfloat16 g_We1t[H_ * D_];    // We1^T [N,K] bf16
__device__ __align__(16) __nv_bfloat16 g_We2t[H_ * H_];
__device__ __align__(16) __nv_bfloat16 g_Wd1t[H_ * 64];    // Wd1^T, K pad 32->64
__device__ __align__(16) __nv_bfloat16 g_Wd2t[H_ * H_];
__device__ __align__(16) __nv_bfloat16 g_Wd3t[D_ * H_];
__device__ __align__(16) __nv_bfloat16 g_zcb[BS_ * 64];    // z_c bf16, padded
__device__ __align__(16) __nv_bfloat16 g_dzb[MNN * 64];    // dz bf16, padded
__device__ __align__(16) __nv_bfloat16 g_h1cb[BS_ * H_];   // center dec h1 (mask1)
__device__ __align__(16) __nv_bfloat16 g_h2cb[BS_ * H_];   // center dec h2 (mask2)
__device__ float g_recon[BS_ * D_];
__device__ float g_w[MNN];
__device__ float g_lpart[768];

// ---------------------------------------------------------------------------
// PTX helpers (plain sm_80+ PTX — assembles for target sm_103)
// ---------------------------------------------------------------------------
__device__ __forceinline__ uint32_t smem_u32(const void* p)
{
    uint32_t a;
    asm("{ .reg .u64 t; cvta.to.shared.u64 t, %1; cvt.u32.u64 %0, t; }"
        : "=r"(a) : "l"(p));
    return a;
}
#define CP_ASYNC16(dst, src) \
    asm volatile("cp.async.cg.shared.global [%0], [%1], 16;" \
                 :: "r"(dst), "l"(src) : "memory")
#define CP_COMMIT()  asm volatile("cp.async.commit_group;" ::: "memory")
#define CP_WAIT1()   asm volatile("cp.async.wait_group 1;" ::: "memory")

__device__ __forceinline__ void ldmx4(uint32_t* r, uint32_t addr)
{
    asm volatile("ldmatrix.sync.aligned.m8n8.x4.shared.b16 {%0,%1,%2,%3}, [%4];"
                 : "=r"(r[0]), "=r"(r[1]), "=r"(r[2]), "=r"(r[3]) : "r"(addr));
}
__device__ __forceinline__ void mma_bf16(float* c, const uint32_t* a,
                                         uint32_t b0, uint32_t b1)
{
    asm volatile(
        "mma.sync.aligned.m16n8k16.row.col.f32.bf16.bf16.f32 "
        "{%0,%1,%2,%3}, {%4,%5,%6,%7}, {%8,%9}, {%0,%1,%2,%3};"
        : "+f"(c[0]), "+f"(c[1]), "+f"(c[2]), "+f"(c[3])
        : "r"(a[0]), "r"(a[1]), "r"(a[2]), "r"(a[3]), "r"(b0), "r"(b1));
}
__device__ __forceinline__ uint32_t sw128(uint32_t o) { return o ^ ((o >> 3) & 0x70); }

// ---------------------------------------------------------------------------
// Warp-MMA GEMM: C[M,N] = A[M,K] @ Bt[N,K]^T  (bf16 in, fp32 accum)
// Block 128x128, BK=64, 8 warps (2x4), warp tile 64x32.
// 3-stage cp.async, prefetch distance 2, one barrier per K-chunk.
// EPI: 1 bias+relu->bf16 | 3 bias->f32 | 4 mask(bf16>0)->bf16 | 5 fused loss
// ---------------------------------------------------------------------------
static constexpr int STAGE_BYTES = 32768;           // A 16KB + B 16KB
static constexpr int SMEM_BYTES  = 3 * STAGE_BYTES; // 96KB -> 2 CTAs/SM

template <int EPI>
__global__ void __launch_bounds__(256, 2) tgemm(
    const __nv_bfloat16* __restrict__ A, const __nv_bfloat16* __restrict__ Bt,
    int K, int N,
    __nv_bfloat16* __restrict__ Cb, float* __restrict__ Cf,
    const float* __restrict__ bias, const __nv_bfloat16* __restrict__ maskp,
    const float* __restrict__ xnn, const float* __restrict__ recon,
    const float* __restrict__ wrow, float* __restrict__ lpart)
{
    extern __shared__ __align__(128) char smem[];
    const uint32_t sb = smem_u32(smem);
    const int tid = threadIdx.x, lane = tid & 31, wid = tid >> 5;
    const int wm = wid & 1, wn = wid >> 1;           // 2 x 4 warp grid
    const int rb = blockIdx.y << 7, cbase = blockIdx.x << 7;

    float acc[4][4][4];
#pragma unroll
    for (int i = 0; i < 4; i++)
#pragma unroll
        for (int j = 0; j < 4; j++)
#pragma unroll
            for (int q = 0; q < 4; q++) acc[i][j][q] = 0.f;

    const int nk = K >> 6;

    const int ldrow = tid >> 3;
    const int ldc   = tid & 7;
    const __nv_bfloat16* Abase = A  + (size_t)(rb + ldrow) * K + ldc * 8;
    const __nv_bfloat16* Bbase = Bt + (size_t)(cbase + ldrow) * K + ldc * 8;

    const int aBase = (wm * 64 + (lane & 15)) * 128 + ((lane >> 4) * 16);
    const int bBase = (wn * 32 + (lane & 7) + ((lane >> 4) * 8)) * 128
                    + (((lane >> 3) & 1) * 16);

#pragma unroll
    for (int s = 0; s < 2; s++) {
        if (s < nk) {
            const uint32_t sa = sb + s * STAGE_BYTES;
#pragma unroll
            for (int i = 0; i < 4; i++) {
                uint32_t sw = sw128((ldrow + i * 32) * 128 + ldc * 16);
                CP_ASYNC16(sa + sw,         Abase + (size_t)(i * 32) * K + s * 64);
                CP_ASYNC16(sa + 16384 + sw, Bbase + (size_t)(i * 32) * K + s * 64);
            }
        }
        CP_COMMIT();
    }

    for (int kc = 0; kc < nk; kc++) {
        CP_WAIT1();
        __syncthreads();

        const int nx = kc + 2;
        if (nx < nk) {
            const uint32_t sn = sb + (nx % 3) * STAGE_BYTES;
#pragma unroll
            for (int i = 0; i < 4; i++) {
                uint32_t sw = sw128((ldrow + i * 32) * 128 + ldc * 16);
                CP_ASYNC16(sn + sw,         Abase + (size_t)(i * 32) * K + nx * 64);
                CP_ASYNC16(sn + 16384 + sw, Bbase + (size_t)(i * 32) * K + nx * 64);
            }
        }
        CP_COMMIT();

        const uint32_t sa = sb + (kc % 3) * STAGE_BYTES;
        const uint32_t sbB = sa + 16384;
#pragma unroll
        for (int ks = 0; ks < 4; ks++) {
            uint32_t a[4][4], b[2][4];
#pragma unroll
            for (int mi = 0; mi < 4; mi++)
                ldmx4(a[mi], sa + sw128(aBase + mi * 2048 + ks * 32));
#pragma unroll
            for (int g = 0; g < 2; g++)
                ldmx4(b[g], sbB + sw128(bBase + g * 2048 + ks * 32));
#pragma unroll
            for (int mi = 0; mi < 4; mi++)
#pragma unroll
                for (int nj = 0; nj < 4; nj++)
                    mma_bf16(acc[mi][nj], a[mi],
                             b[nj >> 1][(nj & 1) * 2], b[nj >> 1][(nj & 1) * 2 + 1]);
        }
    }

    // ---- epilogue
    const int er0 = wm * 64 + (lane >> 2);
    const int ec0 = wn * 32 + (lane & 3) * 2;
    float lsum = 0.f;
#pragma unroll
    for (int mi = 0; mi < 4; mi++) {
#pragma unroll
        for (int half = 0; half < 2; half++) {
            const int r = rb + er0 + mi * 16 + half * 8;
#pragma unroll
            for (int nj = 0; nj < 4; nj++) {
                const int cc = cbase + ec0 + nj * 8;
                float v0 = acc[mi][nj][half * 2];
                float v1 = acc[mi][nj][half * 2 + 1];
                if (EPI == 1) {
                    v0 = fmaxf(v0 + bias[cc], 0.f);
                    v1 = fmaxf(v1 + bias[cc + 1], 0.f);
                    *(__nv_bfloat162*)(Cb + (size_t)r * N + cc) =
                        __floats2bfloat162_rn(v0, v1);
                } else if (EPI == 3) {
                    Cf[(size_t)r * N + cc]     = v0 + bias[cc];
                    Cf[(size_t)r * N + cc + 1] = v1 + bias[cc + 1];
                } else if (EPI == 4) {
                    const __nv_bfloat16* mr = maskp + (size_t)(r >> 5) * N + cc;
                    v0 = (__bfloat162float(mr[0]) > 0.f) ? v0 : 0.f;
                    v1 = (__bfloat162float(mr[1]) > 0.f) ? v1 : 0.f;
                    *(__nv_bfloat162*)(Cb + (size_t)r * N + cc) =
                        __floats2bfloat162_rn(v0, v1);
                } else {   // EPI 5: fused weighted squared error
                    const float* xr = xnn   + (size_t)r * N + cc;
                    const float* rr = recon + (size_t)(r >> 5) * N + cc;
                    float e0 = xr[0] - rr[0] - v0;
                    float e1 = xr[1] - rr[1] - v1;
                    lsum += wrow[r] * (e0 * e0 + e1 * e1);
                }
            }
        }
    }
    if (EPI == 5) {
#pragma unroll
        for (int o = 16; o; o >>= 1) lsum += __shfl_down_sync(0xffffffffu, lsum, o);
        __shared__ float red[8];
        if ((tid & 31) == 0) red[wid] = lsum;
        __syncthreads();
        if (tid == 0) {
            float t = 0.f;
#pragma unroll
            for (int i = 0; i < 8; i++) t += red[i];
            lpart[blockIdx.y * gridDim.x + blockIdx.x] = t;
        }
    }
}

// ---------------------------------------------------------------------------
// Fused conversion + binary-kernel weights (one block per batch row).
// ---------------------------------------------------------------------------
__global__ void __launch_bounds__(256) conv_x_w(
    const float* __restrict__ xc, const float* __restrict__ xnn)
{
    const int r = blockIdx.x;
    if (r < BS_) {
        const float4* src = (const float4*)(xc + (size_t)r * D_);
        __nv_bfloat162* dst = (__nv_bfloat162*)(g_xa + (size_t)r * D_);
#pragma unroll
        for (int i = 0; i < 3; i++) {
            float4 v = src[threadIdx.x + i * 256];
            dst[(threadIdx.x + i * 256) * 2]     = __floats2bfloat162_rn(v.x, v.y);
            dst[(threadIdx.x + i * 256) * 2 + 1] = __floats2bfloat162_rn(v.z, v.w);
        }
        return;
    }
    const int rn = r - BS_;
    const float4* src = (const float4*)(xnn + (size_t)rn * D_);
    const float4* cen = (const float4*)(xc + (size_t)(rn >> 5) * D_);
    __nv_bfloat162* dst = (__nv_bfloat162*)(g_xa + (size_t)r * D_);
    float s = 0.f;
#pragma unroll
    for (int i = 0; i < 3; i++) {
        float4 v = src[threadIdx.x + i * 256];
        float4 c = cen[threadIdx.x + i * 256];
        dst[(threadIdx.x + i * 256) * 2]     = __floats2bfloat162_rn(v.x, v.y);
        dst[(threadIdx.x + i * 256) * 2 + 1] = __floats2bfloat162_rn(v.z, v.w);
        float dx = v.x - c.x, dy = v.y - c.y, dz2 = v.z - c.z, dw = v.w - c.w;
        s += dx * dx + dy * dy + dz2 * dz2 + dw * dw;
    }
#pragma unroll
    for (int o = 16; o; o >>= 1) s += __shfl_down_sync(0xffffffffu, s, o);
    __shared__ float red[8];
    if ((threadIdx.x & 31) == 0) red[threadIdx.x >> 5] = s;
    __syncthreads();
    if (threadIdx.x == 0) {
        float t = 0.f;
#pragma unroll
        for (int i = 0; i < 8; i++) t += red[i];
        g_w[rn] = (t > 1e-24f) ? 1.0f : 0.5f;
    }
}

// W[K,N] f32 -> Wt[N,Kp] bf16 (zero pad K..Kp)
__global__ void __launch_bounds__(256) transpose_bf16(
    const float* __restrict__ in, __nv_bfloat16* __restrict__ out,
    int K, int N, int Kp)
{
    __shared__ float tile[32][33];
    const int kb = blockIdx.y * 32, nb = blockIdx.x * 32;
    const int tx = threadIdx.x & 31, ty = threadIdx.x >> 5;
#pragma unroll
    for (int i = 0; i < 32; i += 8) {
        int k = kb + ty + i, n = nb + tx;
        tile[ty + i][tx] = (k < K && n < N) ? in[(size_t)k * N + n] : 0.f;
    }
    __syncthreads();
#pragma unroll
    for (int i = 0; i < 32; i += 8) {
        int n = nb + ty + i, k = kb + tx;
        out[(size_t)n * Kp + k] = __float2bfloat16(tile[tx][ty + i]);
    }
}

// ---------------------------------------------------------------------------
// fc_z: z = h2b @ We3 (+be3 for centers); emits zcb (centers, padded bf16)
// and dzb (neighbors: z_nn - z_c, bias cancels, padded bf16) directly.
// Neighbor blocks recompute their 2 center z-rows locally (no cross-block dep).
// ---------------------------------------------------------------------------
__global__ void __launch_bounds__(256) fc_z(
    const __nv_bfloat16* __restrict__ A,   // g_h2b
    const float* __restrict__ We3, const float* __restrict__ be3)
{
    __shared__ float As[64][128];
    __shared__ float zc[2][32];
    const int r0 = blockIdx.x * 64;
    const int c = threadIdx.x & 31, rg = threadIdx.x >> 5;
    float acc[8] = {};
    for (int kt = 0; kt < H_; kt += 128) {
        __syncthreads();
        for (int l = threadIdx.x; l < 64 * 64; l += 256) {
            int rr = l >> 6, cc2 = l & 63;
            __nv_bfloat162 v =
                *((const __nv_bfloat162*)(A + (size_t)(r0 + rr) * H_ + kt) + cc2);
            *(float2*)&As[rr][cc2 * 2] =
                make_float2(__bfloat162float(v.x), __bfloat162float(v.y));
        }
        __syncthreads();
        for (int k = 0; k < 128; k++) {
            float b = We3[(size_t)(kt + k) * 32 + c];
#pragma unroll
            for (int i = 0; i < 8; i++) acc[i] += As[rg * 8 + i][k] * b;
        }
    }
    if (r0 < BS_) {
        const float bs = be3[c];
#pragma unroll
        for (int i = 0; i < 8; i++) {
            int r = r0 + rg * 8 + i;
            g_zcb[r * 64 + c]      = __float2bfloat16(acc[i] + bs);
            g_zcb[r * 64 + 32 + c] = __float2bfloat16(0.f);
        }
        return;
    }
    // neighbors: local recompute of the 2 relevant center z-rows (no bias)
    const int rn0 = r0 - BS_;
    const int cbase0 = rn0 >> 5;
    {
        const int outi = threadIdx.x >> 2;   // 0..63
        const int sub  = threadIdx.x & 3;
        const int ci = outi >> 5, j = outi & 31;
        const __nv_bfloat16* hr = A + (size_t)(cbase0 + ci) * H_;
        float s = 0.f;
        for (int k = sub * 256; k < sub * 256 + 256; k += 2) {
            __nv_bfloat162 v = *(const __nv_bfloat162*)(hr + k);
            s += __bfloat162float(v.x) * We3[(size_t)k * 32 + j]
               + __bfloat162float(v.y) * We3[(size_t)(k + 1) * 32 + j];
        }
        s += __shfl_xor_sync(0xffffffffu, s, 1);
        s += __shfl_xor_sync(0xffffffffu, s, 2);
        if (sub == 0) zc[ci][j] = s;
    }
    __syncthreads();
#pragma unroll
    for (int i = 0; i < 8; i++) {
        int rn = rn0 + rg * 8 + i;
        int ci = (rn >> 5) - cbase0;
        g_dzb[(size_t)rn * 64 + c]      = __float2bfloat16(acc[i] - zc[ci][c]);
        g_dzb[(size_t)rn * 64 + 32 + c] = __float2bfloat16(0.f);
    }
}

__global__ void final_reduce(float* __restrict__ out)
{
    float s = 0.f;
    for (int i = threadIdx.x; i < 768; i += 256) s += g_lpart[i];
#pragma unroll
    for (int o = 16; o; o >>= 1) s += __shfl_down_sync(0xffffffffu, s, o);
    __shared__ float red[8];
    if ((threadIdx.x & 31) == 0) red[threadIdx.x >> 5] = s;
    __syncthreads();
    if (threadIdx.x == 0) {
        float t = 0.f;
#pragma unroll
        for (int i = 0; i < 8; i++) t += red[i];
        out[0] = t * (1.0f / (float)(BS_ * NN_));
    }
}

// ---------------------------------------------------------------------------
extern "C" void kernel_launch(void* const* d_in, const int* in_sizes, int n_in,
                              void* d_out, int out_size)
{
    const float* x_c = (const float*)d_in[0];
    const float* x_nn = (const float*)d_in[1];
    const float* We1 = (const float*)d_in[2];
    const float* be1 = (const float*)d_in[3];
    const float* We2 = (const float*)d_in[4];
    const float* be2 = (const float*)d_in[5];
    const float* We3 = (const float*)d_in[6];
    const float* be3 = (const float*)d_in[7];
    const float* Wd1 = (const float*)d_in[8];
    const float* bd1 = (const float*)d_in[9];
    const float* Wd2 = (const float*)d_in[10];
    const float* bd2 = (const float*)d_in[11];
    const float* Wd3 = (const float*)d_in[12];
    const float* bd3 = (const float*)d_in[13];
    float* out = (float*)d_out;

    cudaFuncSetAttribute(tgemm<1>, cudaFuncAttributeMaxDynamicSharedMemorySize, SMEM_BYTES);
    cudaFuncSetAttribute(tgemm<3>, cudaFuncAttributeMaxDynamicSharedMemorySize, SMEM_BYTES);
    cudaFuncSetAttribute(tgemm<4>, cudaFuncAttributeMaxDynamicSharedMemorySize, SMEM_BYTES);
    cudaFuncSetAttribute(tgemm<5>, cudaFuncAttributeMaxDynamicSharedMemorySize, SMEM_BYTES);

    __nv_bfloat16 *xa, *h1b, *h2b, *We1t, *We2t, *Wd1t, *Wd2t, *Wd3t, *zcb, *dzb, *h1cb, *h2cb;
    float *recon, *w, *lpart;
    cudaGetSymbolAddress((void**)&xa, g_xa);
    cudaGetSymbolAddress((void**)&h1b, g_h1b);
    cudaGetSymbolAddress((void**)&h2b, g_h2b);
    cudaGetSymbolAddress((void**)&We1t, g_We1t);
    cudaGetSymbolAddress((void**)&We2t, g_We2t);
    cudaGetSymbolAddress((void**)&Wd1t, g_Wd1t);
    cudaGetSymbolAddress((void**)&Wd2t, g_Wd2t);
    cudaGetSymbolAddress((void**)&Wd3t, g_Wd3t);
    cudaGetSymbolAddress((void**)&zcb, g_zcb);
    cudaGetSymbolAddress((void**)&dzb, g_dzb);
    cudaGetSymbolAddress((void**)&h1cb, g_h1cb);
    cudaGetSymbolAddress((void**)&h2cb, g_h2cb);
    cudaGetSymbolAddress((void**)&recon, g_recon);
    cudaGetSymbolAddress((void**)&w, g_w);
    cudaGetSymbolAddress((void**)&lpart, g_lpart);

    // streams/events forked from the capture (default) stream; joined below.
    cudaStream_t sA, sB;
    cudaStreamCreateWithFlags(&sA, cudaStreamNonBlocking);
    cudaStreamCreateWithFlags(&sB, cudaStreamNonBlocking);
    cudaEvent_t ev0, evA1, evA2, evA3, evC1, evB1, evB2;
    cudaEventCreateWithFlags(&ev0,  cudaEventDisableTiming);
    cudaEventCreateWithFlags(&evA1, cudaEventDisableTiming);
    cudaEventCreateWithFlags(&evA2, cudaEventDisableTiming);
    cudaEventCreateWithFlags(&evA3, cudaEventDisableTiming);
    cudaEventCreateWithFlags(&evC1, cudaEventDisableTiming);
    cudaEventCreateWithFlags(&evB1, cudaEventDisableTiming);
    cudaEventCreateWithFlags(&evB2, cudaEventDisableTiming);

    const dim3 t(256);

    // fork sA: weight transposes off the critical path
    cudaEventRecord(ev0, 0);
    cudaStreamWaitEvent(sA, ev0, 0);
    transpose_bf16<<<dim3(32, 96), 256, 0, sA>>>(We1, We1t, D_, H_, D_);
    cudaEventRecord(evA1, sA);
    transpose_bf16<<<dim3(32, 32), 256, 0, sA>>>(We2, We2t, H_, H_, H_);
    cudaEventRecord(evA2, sA);
    transpose_bf16<<<dim3(32, 2),  256, 0, sA>>>(Wd1, Wd1t, Z_, H_, 64);
    transpose_bf16<<<dim3(32, 32), 256, 0, sA>>>(Wd2, Wd2t, H_, H_, H_);
    transpose_bf16<<<dim3(96, 32), 256, 0, sA>>>(Wd3, Wd3t, H_, D_, H_);
    cudaEventRecord(evA3, sA);

    // main chain on the capture stream
    conv_x_w<<<MALL, 256>>>(x_c, x_nn);
    cudaStreamWaitEvent(0, evA1, 0);
    tgemm<1><<<dim3(8, 33), t, SMEM_BYTES>>>(xa, We1t, D_, H_, h1b, nullptr,
        be1, nullptr, nullptr, nullptr, nullptr, nullptr);
    cudaStreamWaitEvent(0, evA2, 0);
    tgemm<1><<<dim3(8, 33), t, SMEM_BYTES>>>(h1b, We2t, H_, H_, h2b, nullptr,
        be2, nullptr, nullptr, nullptr, nullptr, nullptr);
    fc_z<<<MALL / 64, 256>>>(h2b, We3, be3);

    cudaStreamWaitEvent(0, evA3, 0);
    tgemm<1><<<dim3(8, 1), t, SMEM_BYTES>>>(zcb, Wd1t, 64, H_, h1cb, nullptr,
        bd1, nullptr, nullptr, nullptr, nullptr, nullptr);
    cudaEventRecord(evC1, 0);

    // fork sB: small center-decoder L2/L3 run concurrently with big jvp GEMMs
    cudaStreamWaitEvent(sB, evC1, 0);
    tgemm<1><<<dim3(8, 1), t, SMEM_BYTES, sB>>>(h1cb, Wd2t, H_, H_, h2cb, nullptr,
        bd2, nullptr, nullptr, nullptr, nullptr, nullptr);
    cudaEventRecord(evB1, sB);
    tgemm<3><<<dim3(24, 1), t, SMEM_BYTES, sB>>>(h2cb, Wd3t, H_, D_, nullptr, recon,
        bd3, nullptr, nullptr, nullptr, nullptr, nullptr);
    cudaEventRecord(evB2, sB);

    // jvp chain (hessian term exactly 0 for ReLU decoder)
    tgemm<4><<<dim3(8, 32), t, SMEM_BYTES>>>(dzb, Wd1t, 64, H_, h1b, nullptr,
        nullptr, h1cb, nullptr, nullptr, nullptr, nullptr);
    cudaStreamWaitEvent(0, evB1, 0);
    tgemm<4><<<dim3(8, 32), t, SMEM_BYTES>>>(h1b, Wd2t, H_, H_, h2b, nullptr,
        nullptr, h2cb, nullptr, nullptr, nullptr, nullptr);

    // final GEMM with fused weighted squared-error loss
    cudaStreamWaitEvent(0, evB2, 0);
    tgemm<5><<<dim3(24, 32), t, SMEM_BYTES>>>(h2b, Wd3t, H_, D_, nullptr, nullptr,
        nullptr, nullptr, x_nn, recon, w, lpart);
    final_reduce<<<1, 256>>>(out);

    cudaEventDestroy(ev0);  cudaEventDestroy(evA1); cudaEventDestroy(evA2);
    cudaEventDestroy(evA3); cudaEventDestroy(evC1); cudaEventDestroy(evB1);
    cudaEventDestroy(evB2);
    cudaStreamDestroy(sA);  cudaStreamDestroy(sB);
}

// round 13
// speedup vs baseline: 6.7337x; 1.0203x over previous
#include <cuda_runtime.h>
#include <cuda_bf16.h>
#include <cstdint>

#define D_   3072
#define H_   1024
#define Z_   32
#define BS_  128
#define NN_  32
#define MNN  4096   // BS_*NN_
#define MALL 4224   // BS_ + MNN
#define H1ROWS 2176  // centers(128) + neighbors 0..2047
#define H1NB   2048  // neighbor rows in half 1

// ---------------------------------------------------------------------------
// Static scratch (allocation-free rule)
// ---------------------------------------------------------------------------
__device__ __align__(16) __nv_bfloat16 g_xa[MALL * D_];    // [x_c; x_nn] bf16
__device__ __align__(16) __nv_bfloat16 g_h1b[MALL * H_];   // enc h1
__device__ __align__(16) __nv_bfloat16 g_h2b[MALL * H_];   // enc h2
__device__ __align__(16) __nv_bfloat16 g_t1[MNN * H_];     // jvp t1 (own buffer)
__device__ __align__(16) __nv_bfloat16 g_t2[MNN * H_];     // jvp t2 (own buffer)
__device__ __align__(16) __nv_bfloat16 g_We1t[H_ * D_];    // We1^T [N,K] bf16
__device__ __align__(16) __nv_bfloat16 g_We2t[H_ * H_];
__device__ __align__(16) __nv_bfloat16 g_Wd1t[H_ * 64];    // Wd1^T, K pad 32->64
__device__ __align__(16) __nv_bfloat16 g_Wd2t[H_ * H_];
__device__ __align__(16) __nv_bfloat16 g_Wd3t[D_ * H_];
__device__ __align__(16) __nv_bfloat16 g_zcb[BS_ * 64];    // z_c bf16, padded
__device__ __align__(16) __nv_bfloat16 g_dzb[MNN * 64];    // dz bf16, padded
__device__ __align__(16) __nv_bfloat16 g_h1cb[BS_ * H_];   // center dec h1 (mask1)
__device__ __align__(16) __nv_bfloat16 g_h2cb[BS_ * H_];   // center dec h2 (mask2)
__device__ float g_recon[BS_ * D_];
__device__ float g_w[MNN];
__device__ float g_lpart[768];

// ---------------------------------------------------------------------------
// PTX helpers (plain sm_80+ PTX — assembles for target sm_103)
// ---------------------------------------------------------------------------
__device__ __forceinline__ uint32_t smem_u32(const void* p)
{
    uint32_t a;
    asm("{ .reg .u64 t; cvta.to.shared.u64 t, %1; cvt.u32.u64 %0, t; }"
        : "=r"(a) : "l"(p));
    return a;
}
#define CP_ASYNC16(dst, src) \
    asm volatile("cp.async.cg.shared.global [%0], [%1], 16;" \
                 :: "r"(dst), "l"(src) : "memory")
#define CP_COMMIT()  asm volatile("cp.async.commit_group;" ::: "memory")
#define CP_WAIT1()   asm volatile("cp.async.wait_group 1;" ::: "memory")

__device__ __forceinline__ void ldmx4(uint32_t* r, uint32_t addr)
{
    asm volatile("ldmatrix.sync.aligned.m8n8.x4.shared.b16 {%0,%1,%2,%3}, [%4];"
                 : "=r"(r[0]), "=r"(r[1]), "=r"(r[2]), "=r"(r[3]) : "r"(addr));
}
__device__ __forceinline__ void mma_bf16(float* c, const uint32_t* a,
                                         uint32_t b0, uint32_t b1)
{
    asm volatile(
        "mma.sync.aligned.m16n8k16.row.col.f32.bf16.bf16.f32 "
        "{%0,%1,%2,%3}, {%4,%5,%6,%7}, {%8,%9}, {%0,%1,%2,%3};"
        : "+f"(c[0]), "+f"(c[1]), "+f"(c[2]), "+f"(c[3])
        : "r"(a[0]), "r"(a[1]), "r"(a[2]), "r"(a[3]), "r"(b0), "r"(b1));
}
__device__ __forceinline__ uint32_t sw128(uint32_t o) { return o ^ ((o >> 3) & 0x70); }

// ---------------------------------------------------------------------------
// Warp-MMA GEMM: C[M,N] = A[M,K] @ Bt[N,K]^T  (bf16 in, fp32 accum)
// Block 128x128, BK=64, 8 warps (2x4), warp tile 64x32.
// 3-stage cp.async, prefetch distance 2, one barrier per K-chunk.
// rowoff: global-row offset of A's first row (for mask/recon/w/xnn indexing)
// EPI: 1 bias+relu->bf16 | 3 bias->f32 | 4 mask(bf16>0)->bf16 | 5 fused loss
// ---------------------------------------------------------------------------
static constexpr int STAGE_BYTES = 32768;           // A 16KB + B 16KB
static constexpr int SMEM_BYTES  = 3 * STAGE_BYTES; // 96KB -> 2 CTAs/SM

template <int EPI>
__global__ void __launch_bounds__(256, 2) tgemm(
    const __nv_bfloat16* __restrict__ A, const __nv_bfloat16* __restrict__ Bt,
    int K, int N, int rowoff,
    __nv_bfloat16* __restrict__ Cb, float* __restrict__ Cf,
    const float* __restrict__ bias, const __nv_bfloat16* __restrict__ maskp,
    const float* __restrict__ xnn, const float* __restrict__ recon,
    const float* __restrict__ wrow, float* __restrict__ lpart)
{
    extern __shared__ __align__(128) char smem[];
    const uint32_t sb = smem_u32(smem);
    const int tid = threadIdx.x, lane = tid & 31, wid = tid >> 5;
    const int wm = wid & 1, wn = wid >> 1;           // 2 x 4 warp grid
    const int rb = blockIdx.y << 7, cbase = blockIdx.x << 7;

    float acc[4][4][4];
#pragma unroll
    for (int i = 0; i < 4; i++)
#pragma unroll
        for (int j = 0; j < 4; j++)
#pragma unroll
            for (int q = 0; q < 4; q++) acc[i][j][q] = 0.f;

    const int nk = K >> 6;

    const int ldrow = tid >> 3;
    const int ldc   = tid & 7;
    const __nv_bfloat16* Abase = A  + (size_t)(rb + ldrow) * K + ldc * 8;
    const __nv_bfloat16* Bbase = Bt + (size_t)(cbase + ldrow) * K + ldc * 8;

    const int aBase = (wm * 64 + (lane & 15)) * 128 + ((lane >> 4) * 16);
    const int bBase = (wn * 32 + (lane & 7) + ((lane >> 4) * 8)) * 128
                    + (((lane >> 3) & 1) * 16);

#pragma unroll
    for (int s = 0; s < 2; s++) {
        if (s < nk) {
            const uint32_t sa = sb + s * STAGE_BYTES;
#pragma unroll
            for (int i = 0; i < 4; i++) {
                uint32_t sw = sw128((ldrow + i * 32) * 128 + ldc * 16);
                CP_ASYNC16(sa + sw,         Abase + (size_t)(i * 32) * K + s * 64);
                CP_ASYNC16(sa + 16384 + sw, Bbase + (size_t)(i * 32) * K + s * 64);
            }
        }
        CP_COMMIT();
    }

    for (int kc = 0; kc < nk; kc++) {
        CP_WAIT1();
        __syncthreads();

        const int nx = kc + 2;
        if (nx < nk) {
            const uint32_t sn = sb + (nx % 3) * STAGE_BYTES;
#pragma unroll
            for (int i = 0; i < 4; i++) {
                uint32_t sw = sw128((ldrow + i * 32) * 128 + ldc * 16);
                CP_ASYNC16(sn + sw,         Abase + (size_t)(i * 32) * K + nx * 64);
                CP_ASYNC16(sn + 16384 + sw, Bbase + (size_t)(i * 32) * K + nx * 64);
            }
        }
        CP_COMMIT();

        const uint32_t sa = sb + (kc % 3) * STAGE_BYTES;
        const uint32_t sbB = sa + 16384;
#pragma unroll
        for (int ks = 0; ks < 4; ks++) {
            uint32_t a[4][4], b[2][4];
#pragma unroll
            for (int mi = 0; mi < 4; mi++)
                ldmx4(a[mi], sa + sw128(aBase + mi * 2048 + ks * 32));
#pragma unroll
            for (int g = 0; g < 2; g++)
                ldmx4(b[g], sbB + sw128(bBase + g * 2048 + ks * 32));
#pragma unroll
            for (int mi = 0; mi < 4; mi++)
#pragma unroll
                for (int nj = 0; nj < 4; nj++)
                    mma_bf16(acc[mi][nj], a[mi],
                             b[nj >> 1][(nj & 1) * 2], b[nj >> 1][(nj & 1) * 2 + 1]);
        }
    }

    // ---- epilogue
    const int er0 = wm * 64 + (lane >> 2);
    const int ec0 = wn * 32 + (lane & 3) * 2;
    float lsum = 0.f;
#pragma unroll
    for (int mi = 0; mi < 4; mi++) {
#pragma unroll
        for (int half = 0; half < 2; half++) {
            const int r  = rb + er0 + mi * 16 + half * 8;
            const int gr = r + rowoff;
#pragma unroll
            for (int nj = 0; nj < 4; nj++) {
                const int cc = cbase + ec0 + nj * 8;
                float v0 = acc[mi][nj][half * 2];
                float v1 = acc[mi][nj][half * 2 + 1];
                if (EPI == 1) {
                    v0 = fmaxf(v0 + bias[cc], 0.f);
                    v1 = fmaxf(v1 + bias[cc + 1], 0.f);
                    *(__nv_bfloat162*)(Cb + (size_t)r * N + cc) =
                        __floats2bfloat162_rn(v0, v1);
                } else if (EPI == 3) {
                    Cf[(size_t)r * N + cc]     = v0 + bias[cc];
                    Cf[(size_t)r * N + cc + 1] = v1 + bias[cc + 1];
                } else if (EPI == 4) {
                    const __nv_bfloat16* mr = maskp + (size_t)(gr >> 5) * N + cc;
                    v0 = (__bfloat162float(mr[0]) > 0.f) ? v0 : 0.f;
                    v1 = (__bfloat162float(mr[1]) > 0.f) ? v1 : 0.f;
                    *(__nv_bfloat162*)(Cb + (size_t)r * N + cc) =
                        __floats2bfloat162_rn(v0, v1);
                } else {   // EPI 5: fused weighted squared error
                    const float* xr = xnn   + (size_t)gr * N + cc;
                    const float* rr = recon + (size_t)(gr >> 5) * N + cc;
                    float e0 = xr[0] - rr[0] - v0;
                    float e1 = xr[1] - rr[1] - v1;
                    lsum += wrow[gr] * (e0 * e0 + e1 * e1);
                }
            }
        }
    }
    if (EPI == 5) {
#pragma unroll
        for (int o = 16; o; o >>= 1) lsum += __shfl_down_sync(0xffffffffu, lsum, o);
        __shared__ float red[8];
        if ((tid & 31) == 0) red[wid] = lsum;
        __syncthreads();
        if (tid == 0) {
            float t = 0.f;
#pragma unroll
            for (int i = 0; i < 8; i++) t += red[i];
            lpart[blockIdx.y * gridDim.x + blockIdx.x] = t;
        }
    }
}

// ---------------------------------------------------------------------------
// Fused conversion + binary-kernel weights (one block per batch row).
// ---------------------------------------------------------------------------
__global__ void __launch_bounds__(256) conv_x_w(
    const float* __restrict__ xc, const float* __restrict__ xnn, int roff)
{
    const int r = blockIdx.x + roff;
    if (r < BS_) {
        const float4* src = (const float4*)(xc + (size_t)r * D_);
        __nv_bfloat162* dst = (__nv_bfloat162*)(g_xa + (size_t)r * D_);
#pragma unroll
        for (int i = 0; i < 3; i++) {
            float4 v = src[threadIdx.x + i * 256];
            dst[(threadIdx.x + i * 256) * 2]     = __floats2bfloat162_rn(v.x, v.y);
            dst[(threadIdx.x + i * 256) * 2 + 1] = __floats2bfloat162_rn(v.z, v.w);
        }
        return;
    }
    const int rn = r - BS_;
    const float4* src = (const float4*)(xnn + (size_t)rn * D_);
    const float4* cen = (const float4*)(xc + (size_t)(rn >> 5) * D_);
    __nv_bfloat162* dst = (__nv_bfloat162*)(g_xa + (size_t)r * D_);
    float s = 0.f;
#pragma unroll
    for (int i = 0; i < 3; i++) {
        float4 v = src[threadIdx.x + i * 256];
        float4 c = cen[threadIdx.x + i * 256];
        dst[(threadIdx.x + i * 256) * 2]     = __floats2bfloat162_rn(v.x, v.y);
        dst[(threadIdx.x + i * 256) * 2 + 1] = __floats2bfloat162_rn(v.z, v.w);
        float dx = v.x - c.x, dy = v.y - c.y, dz2 = v.z - c.z, dw = v.w - c.w;
        s += dx * dx + dy * dy + dz2 * dz2 + dw * dw;
    }
#pragma unroll
    for (int o = 16; o; o >>= 1) s += __shfl_down_sync(0xffffffffu, s, o);
    __shared__ float red[8];
    if ((threadIdx.x & 31) == 0) red[threadIdx.x >> 5] = s;
    __syncthreads();
    if (threadIdx.x == 0) {
        float t = 0.f;
#pragma unroll
        for (int i = 0; i < 8; i++) t += red[i];
        g_w[rn] = (t > 1e-24f) ? 1.0f : 0.5f;
    }
}

// W[K,N] f32 -> Wt[N,Kp] bf16 (zero pad K..Kp)
__global__ void __launch_bounds__(256) transpose_bf16(
    const float* __restrict__ in, __nv_bfloat16* __restrict__ out,
    int K, int N, int Kp)
{
    __shared__ float tile[32][33];
    const int kb = blockIdx.y * 32, nb = blockIdx.x * 32;
    const int tx = threadIdx.x & 31, ty = threadIdx.x >> 5;
#pragma unroll
    for (int i = 0; i < 32; i += 8) {
        int k = kb + ty + i, n = nb + tx;
        tile[ty + i][tx] = (k < K && n < N) ? in[(size_t)k * N + n] : 0.f;
    }
    __syncthreads();
#pragma unroll
    for (int i = 0; i < 32; i += 8) {
        int n = nb + ty + i, k = kb + tx;
        out[(size_t)n * Kp + k] = __float2bfloat16(tile[tx][ty + i]);
    }
}

// ---------------------------------------------------------------------------
// fc_z: z = h2b @ We3 (+be3 for centers); emits zcb (centers, padded bf16)
// and dzb (neighbors: z_nn - z_c, bias cancels, padded bf16) directly.
// ---------------------------------------------------------------------------
__global__ void __launch_bounds__(256) fc_z(
    const __nv_bfloat16* __restrict__ A,   // g_h2b
    const float* __restrict__ We3, const float* __restrict__ be3, int boff)
{
    __shared__ float As[64][128];
    __shared__ float zc[2][32];
    const int r0 = (blockIdx.x + boff) * 64;
    const int c = threadIdx.x & 31, rg = threadIdx.x >> 5;
    float acc[8] = {};
    for (int kt = 0; kt < H_; kt += 128) {
        __syncthreads();
        for (int l = threadIdx.x; l < 64 * 64; l += 256) {
            int rr = l >> 6, cc2 = l & 63;
            __nv_bfloat162 v =
                *((const __nv_bfloat162*)(A + (size_t)(r0 + rr) * H_ + kt) + cc2);
            *(float2*)&As[rr][cc2 * 2] =
                make_float2(__bfloat162float(v.x), __bfloat162float(v.y));
        }
        __syncthreads();
        for (int k = 0; k < 128; k++) {
            float b = We3[(size_t)(kt + k) * 32 + c];
#pragma unroll
            for (int i = 0; i < 8; i++) acc[i] += As[rg * 8 + i][k] * b;
        }
    }
    if (r0 < BS_) {
        const float bs = be3[c];
#pragma unroll
        for (int i = 0; i < 8; i++) {
            int r = r0 + rg * 8 + i;
            g_zcb[r * 64 + c]      = __float2bfloat16(acc[i] + bs);
            g_zcb[r * 64 + 32 + c] = __float2bfloat16(0.f);
        }
        return;
    }
    // neighbors: local recompute of the 2 relevant center z-rows (no bias)
    const int rn0 = r0 - BS_;
    const int cbase0 = rn0 >> 5;
    {
        const int outi = threadIdx.x >> 2;   // 0..63
        const int sub  = threadIdx.x & 3;
        const int ci = outi >> 5, j = outi & 31;
        const __nv_bfloat16* hr = A + (size_t)(cbase0 + ci) * H_;
        float s = 0.f;
        for (int k = sub * 256; k < sub * 256 + 256; k += 2) {
            __nv_bfloat162 v = *(const __nv_bfloat162*)(hr + k);
            s += __bfloat162float(v.x) * We3[(size_t)k * 32 + j]
               + __bfloat162float(v.y) * We3[(size_t)(k + 1) * 32 + j];
        }
        s += __shfl_xor_sync(0xffffffffu, s, 1);
        s += __shfl_xor_sync(0xffffffffu, s, 2);
        if (sub == 0) zc[ci][j] = s;
    }
    __syncthreads();
#pragma unroll
    for (int i = 0; i < 8; i++) {
        int rn = rn0 + rg * 8 + i;
        int ci = (rn >> 5) - cbase0;
        g_dzb[(size_t)rn * 64 + c]      = __float2bfloat16(acc[i] - zc[ci][c]);
        g_dzb[(size_t)rn * 64 + 32 + c] = __float2bfloat16(0.f);
    }
}

__global__ void final_reduce(float* __restrict__ out)
{
    float s = 0.f;
    for (int i = threadIdx.x; i < 768; i += 256) s += g_lpart[i];
#pragma unroll
    for (int o = 16; o; o >>= 1) s += __shfl_down_sync(0xffffffffu, s, o);
    __shared__ float red[8];
    if ((threadIdx.x & 31) == 0) red[threadIdx.x >> 5] = s;
    __syncthreads();
    if (threadIdx.x == 0) {
        float t = 0.f;
#pragma unroll
        for (int i = 0; i < 8; i++) t += red[i];
        out[0] = t * (1.0f / (float)(BS_ * NN_));
    }
}

// ---------------------------------------------------------------------------
extern "C" void kernel_launch(void* const* d_in, const int* in_sizes, int n_in,
                              void* d_out, int out_size)
{
    const float* x_c = (const float*)d_in[0];
    const float* x_nn = (const float*)d_in[1];
    const float* We1 = (const float*)d_in[2];
    const float* be1 = (const float*)d_in[3];
    const float* We2 = (const float*)d_in[4];
    const float* be2 = (const float*)d_in[5];
    const float* We3 = (const float*)d_in[6];
    const float* be3 = (const float*)d_in[7];
    const float* Wd1 = (const float*)d_in[8];
    const float* bd1 = (const float*)d_in[9];
    const float* Wd2 = (const float*)d_in[10];
    const float* bd2 = (const float*)d_in[11];
    const float* Wd3 = (const float*)d_in[12];
    const float* bd3 = (const float*)d_in[13];
    float* out = (float*)d_out;

    cudaFuncSetAttribute(tgemm<1>, cudaFuncAttributeMaxDynamicSharedMemorySize, SMEM_BYTES);
    cudaFuncSetAttribute(tgemm<3>, cudaFuncAttributeMaxDynamicSharedMemorySize, SMEM_BYTES);
    cudaFuncSetAttribute(tgemm<4>, cudaFuncAttributeMaxDynamicSharedMemorySize, SMEM_BYTES);
    cudaFuncSetAttribute(tgemm<5>, cudaFuncAttributeMaxDynamicSharedMemorySize, SMEM_BYTES);

    __nv_bfloat16 *xa, *h1b, *h2b, *t1, *t2, *We1t, *We2t, *Wd1t, *Wd2t, *Wd3t,
                  *zcb, *dzb, *h1cb, *h2cb;
    float *recon, *w, *lpart;
    cudaGetSymbolAddress((void**)&xa, g_xa);
    cudaGetSymbolAddress((void**)&h1b, g_h1b);
    cudaGetSymbolAddress((void**)&h2b, g_h2b);
    cudaGetSymbolAddress((void**)&t1, g_t1);
    cudaGetSymbolAddress((void**)&t2, g_t2);
    cudaGetSymbolAddress((void**)&We1t, g_We1t);
    cudaGetSymbolAddress((void**)&We2t, g_We2t);
    cudaGetSymbolAddress((void**)&Wd1t, g_Wd1t);
    cudaGetSymbolAddress((void**)&Wd2t, g_Wd2t);
    cudaGetSymbolAddress((void**)&Wd3t, g_Wd3t);
    cudaGetSymbolAddress((void**)&zcb, g_zcb);
    cudaGetSymbolAddress((void**)&dzb, g_dzb);
    cudaGetSymbolAddress((void**)&h1cb, g_h1cb);
    cudaGetSymbolAddress((void**)&h2cb, g_h2cb);
    cudaGetSymbolAddress((void**)&recon, g_recon);
    cudaGetSymbolAddress((void**)&w, g_w);
    cudaGetSymbolAddress((void**)&lpart, g_lpart);

    cudaStream_t sA, sB;
    cudaStreamCreateWithFlags(&sA, cudaStreamNonBlocking);
    cudaStreamCreateWithFlags(&sB, cudaStreamNonBlocking);
    cudaEvent_t ev0, evW1, evW2, evD1, evD2, evD3, evE2A, evFzA,
                evC1, evC2, evRec, evLB;
    cudaEvent_t* evs[] = {&ev0, &evW1, &evW2, &evD1, &evD2, &evD3, &evE2A,
                          &evFzA, &evC1, &evC2, &evRec, &evLB};
    for (int i = 0; i < 12; i++) cudaEventCreateWithFlags(evs[i], cudaEventDisableTiming);

    const dim3 t(256);
    cudaEventRecord(ev0, 0);
    cudaStreamWaitEvent(sA, ev0, 0);
    cudaStreamWaitEvent(sB, ev0, 0);

    // ---- sA: weight transposes, then the center-decoder chain
    transpose_bf16<<<dim3(32, 96), 256, 0, sA>>>(We1, We1t, D_, H_, D_);
    cudaEventRecord(evW1, sA);
    transpose_bf16<<<dim3(32, 32), 256, 0, sA>>>(We2, We2t, H_, H_, H_);
    cudaEventRecord(evW2, sA);
    transpose_bf16<<<dim3(32, 2),  256, 0, sA>>>(Wd1, Wd1t, Z_, H_, 64);
    cudaEventRecord(evD1, sA);
    transpose_bf16<<<dim3(32, 32), 256, 0, sA>>>(Wd2, Wd2t, H_, H_, H_);
    cudaEventRecord(evD2, sA);
    transpose_bf16<<<dim3(96, 32), 256, 0, sA>>>(Wd3, Wd3t, H_, D_, H_);
    cudaEventRecord(evD3, sA);

    // ---- stream 0: half-1 chain (centers + neighbors 0..2047)
    conv_x_w<<<H1ROWS, 256>>>(x_c, x_nn, 0);
    // ---- sB: half-2 chain (neighbors 2048..4095)
    conv_x_w<<<MALL - H1ROWS, 256, 0, sB>>>(x_c, x_nn, H1ROWS);

    cudaStreamWaitEvent(0, evW1, 0);
    tgemm<1><<<dim3(8, 17), t, SMEM_BYTES>>>(xa, We1t, D_, H_, 0, h1b, nullptr,
        be1, nullptr, nullptr, nullptr, nullptr, nullptr);
    cudaStreamWaitEvent(sB, evW1, 0);
    tgemm<1><<<dim3(8, 16), t, SMEM_BYTES, sB>>>(xa + (size_t)H1ROWS * D_, We1t,
        D_, H_, 0, h1b + (size_t)H1ROWS * H_, nullptr,
        be1, nullptr, nullptr, nullptr, nullptr, nullptr);

    cudaStreamWaitEvent(0, evW2, 0);
    tgemm<1><<<dim3(8, 17), t, SMEM_BYTES>>>(h1b, We2t, H_, H_, 0, h2b, nullptr,
        be2, nullptr, nullptr, nullptr, nullptr, nullptr);
    cudaEventRecord(evE2A, 0);
    cudaStreamWaitEvent(sB, evW2, 0);
    tgemm<1><<<dim3(8, 16), t, SMEM_BYTES, sB>>>(h1b + (size_t)H1ROWS * H_, We2t,
        H_, H_, 0, h2b + (size_t)H1ROWS * H_, nullptr,
        be2, nullptr, nullptr, nullptr, nullptr, nullptr);

    fc_z<<<34, 256>>>(h2b, We3, be3, 0);            // centers + neighbors 0..2047
    cudaEventRecord(evFzA, 0);
    cudaStreamWaitEvent(sB, evE2A, 0);              // center h2 rows live in half-1
    fc_z<<<32, 256, 0, sB>>>(h2b, We3, be3, 34);    // neighbors 2048..4095

    // ---- sA: center decoder chain (masks + recon), hidden under jvp chain
    cudaStreamWaitEvent(sA, evFzA, 0);
    tgemm<1><<<dim3(8, 1), t, SMEM_BYTES, sA>>>(zcb, Wd1t, 64, H_, 0, h1cb, nullptr,
        bd1, nullptr, nullptr, nullptr, nullptr, nullptr);
    cudaEventRecord(evC1, sA);
    tgemm<1><<<dim3(8, 1), t, SMEM_BYTES, sA>>>(h1cb, Wd2t, H_, H_, 0, h2cb, nullptr,
        bd2, nullptr, nullptr, nullptr, nullptr, nullptr);
    cudaEventRecord(evC2, sA);
    tgemm<3><<<dim3(24, 1), t, SMEM_BYTES, sA>>>(h2cb, Wd3t, H_, D_, 0, nullptr, recon,
        bd3, nullptr, nullptr, nullptr, nullptr, nullptr);
    cudaEventRecord(evRec, sA);

    // ---- jvp chain (hessian term exactly 0 for ReLU decoder)
    cudaStreamWaitEvent(0, evD1, 0);
    cudaStreamWaitEvent(0, evC1, 0);
    tgemm<4><<<dim3(8, 16), t, SMEM_BYTES>>>(dzb, Wd1t, 64, H_, 0, t1, nullptr,
        nullptr, h1cb, nullptr, nullptr, nullptr, nullptr);
    cudaStreamWaitEvent(sB, evD1, 0);
    cudaStreamWaitEvent(sB, evC1, 0);
    tgemm<4><<<dim3(8, 16), t, SMEM_BYTES, sB>>>(dzb + (size_t)H1NB * 64, Wd1t,
        64, H_, H1NB, t1 + (size_t)H1NB * H_, nullptr,
        nullptr, h1cb, nullptr, nullptr, nullptr, nullptr);

    cudaStreamWaitEvent(0, evD2, 0);
    cudaStreamWaitEvent(0, evC2, 0);
    tgemm<4><<<dim3(8, 16), t, SMEM_BYTES>>>(t1, Wd2t, H_, H_, 0, t2, nullptr,
        nullptr, h2cb, nullptr, nullptr, nullptr, nullptr);
    cudaStreamWaitEvent(sB, evD2, 0);
    cudaStreamWaitEvent(sB, evC2, 0);
    tgemm<4><<<dim3(8, 16), t, SMEM_BYTES, sB>>>(t1 + (size_t)H1NB * H_, Wd2t,
        H_, H_, H1NB, t2 + (size_t)H1NB * H_, nullptr,
        nullptr, h2cb, nullptr, nullptr, nullptr, nullptr);

    // ---- final loss GEMMs
    cudaStreamWaitEvent(0, evD3, 0);
    cudaStreamWaitEvent(0, evRec, 0);
    tgemm<5><<<dim3(24, 16), t, SMEM_BYTES>>>(t2, Wd3t, H_, D_, 0, nullptr, nullptr,
        nullptr, nullptr, x_nn, recon, w, lpart);
    cudaStreamWaitEvent(sB, evD3, 0);
    cudaStreamWaitEvent(sB, evRec, 0);
    tgemm<5><<<dim3(24, 16), t, SMEM_BYTES, sB>>>(t2 + (size_t)H1NB * H_, Wd3t,
        H_, D_, H1NB, nullptr, nullptr,
        nullptr, nullptr, x_nn, recon, w, lpart + 384);
    cudaEventRecord(evLB, sB);

    cudaStreamWaitEvent(0, evLB, 0);
    final_reduce<<<1, 256>>>(out);

    for (int i = 0; i < 12; i++) cudaEventDestroy(*evs[i]);
    cudaStreamDestroy(sA);
    cudaStreamDestroy(sB);
}